// round 1
// baseline (speedup 1.0000x reference)
#include <cuda_runtime.h>
#include <math.h>

#define TOKENS 100352      // 32 * 56 * 56  == 2048 windows * 49
#define D      384
#define D3     1152
#define DH     1536
#define NWIN   2048
#define HEADS  12

// -------- scratch (device globals; no allocation allowed) --------
__device__ float g_xw [(size_t)TOKENS * D];   // LN1-out (window order) / LN2-out (token order)
__device__ float g_qkv[(size_t)TOKENS * D3];
__device__ float g_att[(size_t)TOKENS * D];   // attention output, window order
__device__ float g_x1 [(size_t)TOKENS * D];   // after proj + residual, token order
__device__ float g_h  [(size_t)TOKENS * DH];  // mlp hidden
__device__ float g_bias[HEADS * 49 * 49];     // CRPB table

// ================= CRPB bias table =================
__global__ void bias_kernel(const float* __restrict__ w1, const float* __restrict__ b1,
                            const float* __restrict__ w2, const float* __restrict__ b2) {
    int p = blockIdx.x;           // pair index 0..2400 (i*49+j)
    int i = p / 49, j = p % 49;
    float dr = (float)(i / 7 - j / 7);
    float dc = (float)(i % 7 - j % 7);
    float r0 = (dr == 0.f) ? 0.f : copysignf(log1pf(fabsf(dr)), dr);
    float r1 = (dc == 0.f) ? 0.f : copysignf(log1pf(fabsf(dc)), dc);
    __shared__ float hid[64];
    int t = threadIdx.x;
    if (t < 64) {
        float v = r0 * w1[t] + r1 * w1[64 + t] + b1[t];
        hid[t] = fmaxf(v, 0.f);
    }
    __syncthreads();
    if (t < HEADS) {
        float s = b2[t];
        #pragma unroll 8
        for (int k = 0; k < 64; k++) s += hid[k] * w2[k * HEADS + t];
        g_bias[t * 2401 + p] = s;
    }
}

// ================= LayerNorm (optionally fused shift+window-partition gather) =================
__global__ void ln_kernel(const float* __restrict__ x, const float* __restrict__ g,
                          const float* __restrict__ b, float* __restrict__ out, int mapped) {
    int r = blockIdx.x;
    int src = r;
    if (mapped) {
        int win = r / 49, pos = r % 49;
        int bb = win >> 6, wrem = win & 63;
        int wh = wrem >> 3, ww = wrem & 7;
        int rr = pos / 7, cc = pos % 7;
        int sh = (wh * 7 + rr + 3) % 56;
        int sw = (ww * 7 + cc + 3) % 56;
        src = bb * 3136 + sh * 56 + sw;
    }
    const float* xr = x + (size_t)src * D;
    int t = threadIdx.x;                       // 128 threads
    float v0 = xr[t], v1 = xr[t + 128], v2 = xr[t + 256];
    float s = v0 + v1 + v2;
    __shared__ float red[4];
    __shared__ float red2[4];
    #pragma unroll
    for (int o = 16; o > 0; o >>= 1) s += __shfl_down_sync(0xffffffffu, s, o);
    if ((t & 31) == 0) red[t >> 5] = s;
    __syncthreads();
    float mu = (red[0] + red[1] + red[2] + red[3]) * (1.f / 384.f);
    float d0 = v0 - mu, d1 = v1 - mu, d2 = v2 - mu;
    float q = d0 * d0 + d1 * d1 + d2 * d2;
    #pragma unroll
    for (int o = 16; o > 0; o >>= 1) q += __shfl_down_sync(0xffffffffu, q, o);
    if ((t & 31) == 0) red2[t >> 5] = q;
    __syncthreads();
    float var = (red2[0] + red2[1] + red2[2] + red2[3]) * (1.f / 384.f);
    float inv = rsqrtf(var + 1e-5f);
    float* orow = out + (size_t)r * D;
    orow[t]       = d0 * inv * g[t]       + b[t];
    orow[t + 128] = d1 * inv * g[t + 128] + b[t + 128];
    orow[t + 256] = d2 * inv * g[t + 256] + b[t + 256];
}

// ================= tiled fp32 GEMM, C = A(MxK) * W(KxN) + bias =================
// MODE 0: plain   MODE 1: gelu(exact)   MODE 2: proj scatter + residual   MODE 3: out + residual
template <int MODE>
__global__ void gemm_kernel(const float* __restrict__ A, const float* __restrict__ W,
                            const float* __restrict__ bias, float* __restrict__ C,
                            int M, int N, int K, const float* __restrict__ add) {
    __shared__ float As[16][64];
    __shared__ float Bs[16][64];
    int tid = threadIdx.x;                 // 256
    int bm = blockIdx.y * 64;
    int bn = blockIdx.x * 64;
    int tx = tid & 15, ty = tid >> 4;
    int ar = tid >> 2;                     // 0..63 rows of A tile
    int ac = (tid & 3) * 4;                // 0,4,8,12
    int br = tid >> 4;                     // 0..15 rows of B tile
    int bc = (tid & 15) * 4;
    const float* Aptr = A + (size_t)(bm + ar) * K + ac;
    const float* Wptr = W + (size_t)br * N + bn + bc;
    float acc[4][4] = {};
    for (int k0 = 0; k0 < K; k0 += 16) {
        float4 a4 = *(const float4*)(Aptr + k0);
        As[ac + 0][ar] = a4.x; As[ac + 1][ar] = a4.y;
        As[ac + 2][ar] = a4.z; As[ac + 3][ar] = a4.w;
        *(float4*)&Bs[br][bc] = *(const float4*)(Wptr + (size_t)k0 * N);
        __syncthreads();
        #pragma unroll
        for (int k = 0; k < 16; k++) {
            float4 av = *(const float4*)&As[k][ty * 4];
            float4 bv = *(const float4*)&Bs[k][tx * 4];
            float a[4] = {av.x, av.y, av.z, av.w};
            float bb2[4] = {bv.x, bv.y, bv.z, bv.w};
            #pragma unroll
            for (int i = 0; i < 4; i++)
                #pragma unroll
                for (int j = 0; j < 4; j++) acc[i][j] += a[i] * bb2[j];
        }
        __syncthreads();
    }
    int col = bn + tx * 4;
    float b4[4] = {bias[col], bias[col + 1], bias[col + 2], bias[col + 3]};
    #pragma unroll
    for (int i = 0; i < 4; i++) {
        int row = bm + ty * 4 + i;
        if (MODE == 2) {
            int win = row / 49, pos = row % 49;
            int bb = win >> 6, wrem = win & 63;
            int wh = wrem >> 3, ww = wrem & 7;
            int rr = pos / 7, cc = pos % 7;
            int dst = bb * 3136 + ((wh * 7 + rr + 3) % 56) * 56 + ((ww * 7 + cc + 3) % 56);
            float* cp = C + (size_t)dst * N + col;
            const float* ap = add + (size_t)dst * N + col;
            #pragma unroll
            for (int j = 0; j < 4; j++) cp[j] = acc[i][j] + b4[j] + ap[j];
        } else {
            float v[4];
            #pragma unroll
            for (int j = 0; j < 4; j++) v[j] = acc[i][j] + b4[j];
            if (MODE == 1) {
                #pragma unroll
                for (int j = 0; j < 4; j++)
                    v[j] = 0.5f * v[j] * (1.f + erff(v[j] * 0.70710678118654752f));
            }
            if (MODE == 3) {
                const float* ap = add + (size_t)row * N + col;
                #pragma unroll
                for (int j = 0; j < 4; j++) v[j] += ap[j];
            }
            float4 o = {v[0], v[1], v[2], v[3]};
            *(float4*)(C + (size_t)row * N + col) = o;
        }
    }
}

// ================= window attention: one block per (window, head) =================
__global__ void attn_kernel(const float* __restrict__ tau) {
    int blk = blockIdx.x;
    int win = blk / HEADS;
    int head = blk % HEADS;
    __shared__ float qs[49][32], ks[49][32], vs[49][32];
    __shared__ float S[49][52];
    __shared__ int lab[49];
    int t = threadIdx.x;                // 256
    // region labels for the shifted-window mask (computed from label image, no roll)
    int wrem = win & 63;
    int wh = wrem >> 3, ww = wrem & 7;
    if (t < 49) {
        int rr = t / 7, cc = t % 7;
        int h = wh * 7 + rr, w = ww * 7 + cc;
        int hs = (h < 49) ? 0 : ((h < 53) ? 1 : 2);
        int wsg = (w < 49) ? 0 : ((w < 53) ? 1 : 2);
        lab[t] = hs * 3 + wsg;
    }
    const float* base = g_qkv + (size_t)win * 49 * D3 + head * 32;
    for (int idx = t; idx < 49 * 32; idx += 256) {
        int i = idx >> 5, d = idx & 31;
        const float* p = base + (size_t)i * D3 + d;
        qs[i][d] = p[0];
        ks[i][d] = p[384];
        vs[i][d] = p[768];
    }
    __syncthreads();
    if (t < 98) {                        // cosine normalize q (t<49) and k rows
        int i = (t < 49) ? t : (t - 49);
        float* row = (t < 49) ? qs[i] : ks[i];
        float ss = 0.f;
        #pragma unroll
        for (int d = 0; d < 32; d++) ss += row[d] * row[d];
        float inv = 1.f / fmaxf(sqrtf(ss), 1e-12f);
        #pragma unroll
        for (int d = 0; d < 32; d++) row[d] *= inv;
    }
    __syncthreads();
    float tauv = tau[head];
    const float* bh = g_bias + head * 2401;
    for (int idx = t; idx < 2401; idx += 256) {
        int i = idx / 49, j = idx % 49;
        float s = 0.f;
        #pragma unroll
        for (int d = 0; d < 32; d++) s += qs[i][d] * ks[j][d];
        s = s * tauv + bh[idx];
        if (lab[i] != lab[j]) s -= 100.f;
        S[i][j] = s;
    }
    __syncthreads();
    if (t < 49) {
        float m = -1e30f;
        #pragma unroll 7
        for (int j = 0; j < 49; j++) m = fmaxf(m, S[t][j]);
        float sum = 0.f;
        #pragma unroll 7
        for (int j = 0; j < 49; j++) { float e = __expf(S[t][j] - m); S[t][j] = e; sum += e; }
        float inv = 1.f / sum;
        #pragma unroll 7
        for (int j = 0; j < 49; j++) S[t][j] *= inv;
    }
    __syncthreads();
    float* outbase = g_att + (size_t)win * 49 * D + head * 32;
    for (int idx = t; idx < 49 * 32; idx += 256) {
        int i = idx >> 5, d = idx & 31;
        float s = 0.f;
        #pragma unroll 7
        for (int j = 0; j < 49; j++) s += S[i][j] * vs[j][d];
        outbase[(size_t)i * D + d] = s;
    }
}

// ================= launch =================
extern "C" void kernel_launch(void* const* d_in, const int* in_sizes, int n_in,
                              void* d_out, int out_size) {
    const float* x       = (const float*)d_in[0];
    const float* n1g     = (const float*)d_in[1];
    const float* n1b     = (const float*)d_in[2];
    const float* qkv_w   = (const float*)d_in[3];
    const float* qkv_b   = (const float*)d_in[4];
    const float* tau     = (const float*)d_in[5];
    const float* proj_w  = (const float*)d_in[6];
    const float* proj_b  = (const float*)d_in[7];
    const float* crpb_w1 = (const float*)d_in[8];
    const float* crpb_b1 = (const float*)d_in[9];
    const float* crpb_w2 = (const float*)d_in[10];
    const float* crpb_b2 = (const float*)d_in[11];
    const float* n2g     = (const float*)d_in[12];
    const float* n2b     = (const float*)d_in[13];
    const float* mlp_w1  = (const float*)d_in[14];
    const float* mlp_b1  = (const float*)d_in[15];
    const float* mlp_w2  = (const float*)d_in[16];
    const float* mlp_b2  = (const float*)d_in[17];
    float* out = (float*)d_out;

    float *xw, *qkv, *att, *x1, *hbuf;
    cudaGetSymbolAddress((void**)&xw,  g_xw);
    cudaGetSymbolAddress((void**)&qkv, g_qkv);
    cudaGetSymbolAddress((void**)&att, g_att);
    cudaGetSymbolAddress((void**)&x1,  g_x1);
    cudaGetSymbolAddress((void**)&hbuf, g_h);

    const int MB = TOKENS / 64;   // 1568

    bias_kernel<<<2401, 64>>>(crpb_w1, crpb_b1, crpb_w2, crpb_b2);
    ln_kernel<<<TOKENS, 128>>>(x, n1g, n1b, xw, 1);
    gemm_kernel<0><<<dim3(D3 / 64, MB), 256>>>(xw, qkv_w, qkv_b, qkv, TOKENS, D3, D, nullptr);
    attn_kernel<<<NWIN * HEADS, 256>>>(tau);
    gemm_kernel<2><<<dim3(D / 64, MB), 256>>>(att, proj_w, proj_b, x1, TOKENS, D, D, x);
    ln_kernel<<<TOKENS, 128>>>(x1, n2g, n2b, xw, 0);
    gemm_kernel<1><<<dim3(DH / 64, MB), 256>>>(xw, mlp_w1, mlp_b1, hbuf, TOKENS, DH, D, nullptr);
    gemm_kernel<3><<<dim3(D / 64, MB), 256>>>(hbuf, mlp_w2, mlp_b2, out, TOKENS, D, DH, x1);
}

// round 2
// speedup vs baseline: 2.0114x; 2.0114x over previous
#include <cuda_runtime.h>
#include <math.h>

#define TOKENS 100352      // 32 * 56 * 56  == 2048 windows * 49
#define D      384
#define D3     1152
#define DH     1536
#define NWIN   2048
#define HEADS  12

// -------- scratch (device globals; no allocation allowed) --------
__device__ float g_xw [(size_t)TOKENS * D];   // LN1-out (window order) / LN2-out (token order)
__device__ float g_qkv[(size_t)TOKENS * D3];
__device__ float g_att[(size_t)TOKENS * D];   // attention output, window order
__device__ float g_x1 [(size_t)TOKENS * D];   // after proj + residual, token order
__device__ float g_h  [(size_t)TOKENS * DH];  // mlp hidden
__device__ float g_bias[HEADS * 49 * 49];     // CRPB table

// ================= CRPB bias table =================
__global__ void bias_kernel(const float* __restrict__ w1, const float* __restrict__ b1,
                            const float* __restrict__ w2, const float* __restrict__ b2) {
    int p = blockIdx.x;           // pair index 0..2400 (i*49+j)
    int i = p / 49, j = p % 49;
    float dr = (float)(i / 7 - j / 7);
    float dc = (float)(i % 7 - j % 7);
    float r0 = (dr == 0.f) ? 0.f : copysignf(log1pf(fabsf(dr)), dr);
    float r1 = (dc == 0.f) ? 0.f : copysignf(log1pf(fabsf(dc)), dc);
    __shared__ float hid[64];
    int t = threadIdx.x;
    if (t < 64) {
        float v = r0 * w1[t] + r1 * w1[64 + t] + b1[t];
        hid[t] = fmaxf(v, 0.f);
    }
    __syncthreads();
    if (t < HEADS) {
        float s = b2[t];
        #pragma unroll 8
        for (int k = 0; k < 64; k++) s += hid[k] * w2[k * HEADS + t];
        g_bias[t * 2401 + p] = s;
    }
}

// ================= LayerNorm (optionally fused shift+window-partition gather) =================
__global__ void ln_kernel(const float* __restrict__ x, const float* __restrict__ g,
                          const float* __restrict__ b, float* __restrict__ out, int mapped) {
    int r = blockIdx.x;
    int src = r;
    if (mapped) {
        int win = r / 49, pos = r % 49;
        int bb = win >> 6, wrem = win & 63;
        int wh = wrem >> 3, ww = wrem & 7;
        int rr = pos / 7, cc = pos % 7;
        int sh = (wh * 7 + rr + 3) % 56;
        int sw = (ww * 7 + cc + 3) % 56;
        src = bb * 3136 + sh * 56 + sw;
    }
    const float* xr = x + (size_t)src * D;
    int t = threadIdx.x;                       // 128 threads
    float v0 = xr[t], v1 = xr[t + 128], v2 = xr[t + 256];
    float s = v0 + v1 + v2;
    __shared__ float red[4];
    __shared__ float red2[4];
    #pragma unroll
    for (int o = 16; o > 0; o >>= 1) s += __shfl_down_sync(0xffffffffu, s, o);
    if ((t & 31) == 0) red[t >> 5] = s;
    __syncthreads();
    float mu = (red[0] + red[1] + red[2] + red[3]) * (1.f / 384.f);
    float d0 = v0 - mu, d1 = v1 - mu, d2 = v2 - mu;
    float q = d0 * d0 + d1 * d1 + d2 * d2;
    #pragma unroll
    for (int o = 16; o > 0; o >>= 1) q += __shfl_down_sync(0xffffffffu, q, o);
    if ((t & 31) == 0) red2[t >> 5] = q;
    __syncthreads();
    float var = (red2[0] + red2[1] + red2[2] + red2[3]) * (1.f / 384.f);
    float inv = rsqrtf(var + 1e-5f);
    float* orow = out + (size_t)r * D;
    orow[t]       = d0 * inv * g[t]       + b[t];
    orow[t + 128] = d1 * inv * g[t + 128] + b[t + 128];
    orow[t + 256] = d2 * inv * g[t + 256] + b[t + 256];
}

// ================= tf32 tensor-core GEMM =================
// C(MxN) = A(MxK) * W(KxN) + bias, fp32 in/out, tf32 mma accumulate fp32.
// MODE 0: plain   MODE 1: gelu(exact)   MODE 2: proj scatter + residual   MODE 3: out + residual

__device__ __forceinline__ unsigned f2tf32(float x) {
    unsigned r;
    asm("cvt.rna.tf32.f32 %0, %1;" : "=r"(r) : "f"(x));
    return r;
}

__device__ __forceinline__ void mma_tf32(float* c, const unsigned* a, const unsigned* b) {
    asm volatile(
        "mma.sync.aligned.m16n8k8.row.col.f32.tf32.tf32.f32 "
        "{%0,%1,%2,%3}, {%4,%5,%6,%7}, {%8,%9}, {%0,%1,%2,%3};"
        : "+f"(c[0]), "+f"(c[1]), "+f"(c[2]), "+f"(c[3])
        : "r"(a[0]), "r"(a[1]), "r"(a[2]), "r"(a[3]), "r"(b[0]), "r"(b[1]));
}

template <int MODE>
__global__ __launch_bounds__(256) void gemm_tc(
    const float* __restrict__ A, const float* __restrict__ W,
    const float* __restrict__ bias, float* __restrict__ C,
    int M, int N, int K, const float* __restrict__ add) {
    __shared__ unsigned As[16][132];   // [k][m], tf32 bit patterns
    __shared__ unsigned Bs[16][132];   // [k][n]
    int tid = threadIdx.x;
    int bm = blockIdx.y * 128, bn = blockIdx.x * 128;
    int lane = tid & 31, warp = tid >> 5;
    int wm = (warp & 3) * 32, wn = (warp >> 2) * 64;
    int km = lane & 3;        // k within group of 4
    int mrow = lane >> 2;     // 0..7 (also n-group for B)

    // gmem staging indices
    int arow = tid >> 2, acol = (tid & 3) * 4;     // A rows: arow, arow+64
    int brow = tid >> 5, bcol = (tid & 31) * 4;    // B rows: brow, brow+8

    const float* Ap = A + (size_t)(bm + arow) * K + acol;
    const float* Wp = W + (size_t)brow * N + bn + bcol;

    float acc[2][8][4];
    #pragma unroll
    for (int i = 0; i < 2; i++)
        #pragma unroll
        for (int j = 0; j < 8; j++)
            #pragma unroll
            for (int l = 0; l < 4; l++) acc[i][j][l] = 0.f;

    float4 ra0 = *(const float4*)(Ap);
    float4 ra1 = *(const float4*)(Ap + (size_t)64 * K);
    float4 rb0 = *(const float4*)(Wp);
    float4 rb1 = *(const float4*)(Wp + (size_t)8 * N);

    for (int k0 = 0; k0 < K; k0 += 16) {
        As[acol + 0][arow] = f2tf32(ra0.x);
        As[acol + 1][arow] = f2tf32(ra0.y);
        As[acol + 2][arow] = f2tf32(ra0.z);
        As[acol + 3][arow] = f2tf32(ra0.w);
        As[acol + 0][arow + 64] = f2tf32(ra1.x);
        As[acol + 1][arow + 64] = f2tf32(ra1.y);
        As[acol + 2][arow + 64] = f2tf32(ra1.z);
        As[acol + 3][arow + 64] = f2tf32(ra1.w);
        Bs[brow][bcol + 0] = f2tf32(rb0.x);
        Bs[brow][bcol + 1] = f2tf32(rb0.y);
        Bs[brow][bcol + 2] = f2tf32(rb0.z);
        Bs[brow][bcol + 3] = f2tf32(rb0.w);
        Bs[brow + 8][bcol + 0] = f2tf32(rb1.x);
        Bs[brow + 8][bcol + 1] = f2tf32(rb1.y);
        Bs[brow + 8][bcol + 2] = f2tf32(rb1.z);
        Bs[brow + 8][bcol + 3] = f2tf32(rb1.w);
        __syncthreads();

        if (k0 + 16 < K) {   // prefetch next tile while computing
            ra0 = *(const float4*)(Ap + k0 + 16);
            ra1 = *(const float4*)(Ap + (size_t)64 * K + k0 + 16);
            rb0 = *(const float4*)(Wp + (size_t)(k0 + 16) * N);
            rb1 = *(const float4*)(Wp + (size_t)(k0 + 24) * N);
        }

        #pragma unroll
        for (int ks = 0; ks < 16; ks += 8) {
            unsigned af[2][4];
            #pragma unroll
            for (int mi = 0; mi < 2; mi++) {
                int m = wm + mi * 16 + mrow;
                af[mi][0] = As[ks + km][m];
                af[mi][1] = As[ks + km][m + 8];
                af[mi][2] = As[ks + km + 4][m];
                af[mi][3] = As[ks + km + 4][m + 8];
            }
            unsigned bf[8][2];
            #pragma unroll
            for (int ni = 0; ni < 8; ni++) {
                int n = wn + ni * 8 + mrow;
                bf[ni][0] = Bs[ks + km][n];
                bf[ni][1] = Bs[ks + km + 4][n];
            }
            #pragma unroll
            for (int mi = 0; mi < 2; mi++)
                #pragma unroll
                for (int ni = 0; ni < 8; ni++)
                    mma_tf32(acc[mi][ni], af[mi], bf[ni]);
        }
        __syncthreads();
    }

    // ---------- epilogue ----------
    int cbase = bn + wn + 2 * km;
    #pragma unroll
    for (int mi = 0; mi < 2; mi++) {
        #pragma unroll
        for (int half = 0; half < 2; half++) {
            int row = bm + wm + mi * 16 + mrow + half * 8;
            int dst = row;
            if (MODE == 2) {
                int win = row / 49, pos = row % 49;
                int bb = win >> 6, wrem = win & 63;
                int wh = wrem >> 3, ww = wrem & 7;
                int rr = pos / 7, cc = pos % 7;
                dst = bb * 3136 + ((wh * 7 + rr + 3) % 56) * 56 + ((ww * 7 + cc + 3) % 56);
            }
            float* cp = C + (size_t)dst * N;
            const float* ap = (MODE == 2 || MODE == 3) ? add + (size_t)dst * N : nullptr;
            #pragma unroll
            for (int ni = 0; ni < 8; ni++) {
                int col = cbase + ni * 8;
                float v0 = acc[mi][ni][half * 2 + 0] + bias[col];
                float v1 = acc[mi][ni][half * 2 + 1] + bias[col + 1];
                if (MODE == 1) {
                    v0 = 0.5f * v0 * (1.f + erff(v0 * 0.70710678118654752f));
                    v1 = 0.5f * v1 * (1.f + erff(v1 * 0.70710678118654752f));
                }
                if (MODE == 2 || MODE == 3) {
                    v0 += ap[col];
                    v1 += ap[col + 1];
                }
                float2 o = {v0, v1};
                *(float2*)(cp + col) = o;
            }
        }
    }
}

// ================= window attention: one block per (window, head) =================
__global__ void attn_kernel(const float* __restrict__ tau) {
    int blk = blockIdx.x;
    int win = blk / HEADS;
    int head = blk % HEADS;
    __shared__ float qs[49][32], ks[49][32], vs[49][32];
    __shared__ float S[49][52];
    __shared__ int lab[49];
    int t = threadIdx.x;                // 256
    int wrem = win & 63;
    int wh = wrem >> 3, ww = wrem & 7;
    if (t < 49) {
        int rr = t / 7, cc = t % 7;
        int h = wh * 7 + rr, w = ww * 7 + cc;
        int hs = (h < 49) ? 0 : ((h < 53) ? 1 : 2);
        int wsg = (w < 49) ? 0 : ((w < 53) ? 1 : 2);
        lab[t] = hs * 3 + wsg;
    }
    const float* base = g_qkv + (size_t)win * 49 * D3 + head * 32;
    for (int idx = t; idx < 49 * 32; idx += 256) {
        int i = idx >> 5, d = idx & 31;
        const float* p = base + (size_t)i * D3 + d;
        qs[i][d] = p[0];
        ks[i][d] = p[384];
        vs[i][d] = p[768];
    }
    __syncthreads();
    if (t < 98) {                        // cosine normalize q (t<49) and k rows
        int i = (t < 49) ? t : (t - 49);
        float* row = (t < 49) ? qs[i] : ks[i];
        float ss = 0.f;
        #pragma unroll
        for (int d = 0; d < 32; d++) ss += row[d] * row[d];
        float inv = 1.f / fmaxf(sqrtf(ss), 1e-12f);
        #pragma unroll
        for (int d = 0; d < 32; d++) row[d] *= inv;
    }
    __syncthreads();
    float tauv = tau[head];
    const float* bh = g_bias + head * 2401;
    for (int idx = t; idx < 2401; idx += 256) {
        int i = idx / 49, j = idx % 49;
        float s = 0.f;
        #pragma unroll
        for (int d = 0; d < 32; d++) s += qs[i][d] * ks[j][d];
        s = s * tauv + bh[idx];
        if (lab[i] != lab[j]) s -= 100.f;
        S[i][j] = s;
    }
    __syncthreads();
    if (t < 49) {
        float m = -1e30f;
        #pragma unroll 7
        for (int j = 0; j < 49; j++) m = fmaxf(m, S[t][j]);
        float sum = 0.f;
        #pragma unroll 7
        for (int j = 0; j < 49; j++) { float e = __expf(S[t][j] - m); S[t][j] = e; sum += e; }
        float inv = 1.f / sum;
        #pragma unroll 7
        for (int j = 0; j < 49; j++) S[t][j] *= inv;
    }
    __syncthreads();
    float* outbase = g_att + (size_t)win * 49 * D + head * 32;
    for (int idx = t; idx < 49 * 32; idx += 256) {
        int i = idx >> 5, d = idx & 31;
        float s = 0.f;
        #pragma unroll 7
        for (int j = 0; j < 49; j++) s += S[i][j] * vs[j][d];
        outbase[(size_t)i * D + d] = s;
    }
}

// ================= launch =================
extern "C" void kernel_launch(void* const* d_in, const int* in_sizes, int n_in,
                              void* d_out, int out_size) {
    const float* x       = (const float*)d_in[0];
    const float* n1g     = (const float*)d_in[1];
    const float* n1b     = (const float*)d_in[2];
    const float* qkv_w   = (const float*)d_in[3];
    const float* qkv_b   = (const float*)d_in[4];
    const float* tau     = (const float*)d_in[5];
    const float* proj_w  = (const float*)d_in[6];
    const float* proj_b  = (const float*)d_in[7];
    const float* crpb_w1 = (const float*)d_in[8];
    const float* crpb_b1 = (const float*)d_in[9];
    const float* crpb_w2 = (const float*)d_in[10];
    const float* crpb_b2 = (const float*)d_in[11];
    const float* n2g     = (const float*)d_in[12];
    const float* n2b     = (const float*)d_in[13];
    const float* mlp_w1  = (const float*)d_in[14];
    const float* mlp_b1  = (const float*)d_in[15];
    const float* mlp_w2  = (const float*)d_in[16];
    const float* mlp_b2  = (const float*)d_in[17];
    float* out = (float*)d_out;

    float *xw, *qkv, *att, *x1, *hbuf;
    cudaGetSymbolAddress((void**)&xw,  g_xw);
    cudaGetSymbolAddress((void**)&qkv, g_qkv);
    cudaGetSymbolAddress((void**)&att, g_att);
    cudaGetSymbolAddress((void**)&x1,  g_x1);
    cudaGetSymbolAddress((void**)&hbuf, g_h);

    const int MB = TOKENS / 128;   // 784

    bias_kernel<<<2401, 64>>>(crpb_w1, crpb_b1, crpb_w2, crpb_b2);
    ln_kernel<<<TOKENS, 128>>>(x, n1g, n1b, xw, 1);
    gemm_tc<0><<<dim3(D3 / 128, MB), 256>>>(xw, qkv_w, qkv_b, qkv, TOKENS, D3, D, nullptr);
    attn_kernel<<<NWIN * HEADS, 256>>>(tau);
    gemm_tc<2><<<dim3(D / 128, MB), 256>>>(att, proj_w, proj_b, x1, TOKENS, D, D, x);
    ln_kernel<<<TOKENS, 128>>>(x1, n2g, n2b, xw, 0);
    gemm_tc<1><<<dim3(DH / 128, MB), 256>>>(xw, mlp_w1, mlp_b1, hbuf, TOKENS, DH, D, nullptr);
    gemm_tc<3><<<dim3(D / 128, MB), 256>>>(hbuf, mlp_w2, mlp_b2, out, TOKENS, D, DH, x1);
}

// round 3
// speedup vs baseline: 2.1659x; 1.0768x over previous
#include <cuda_runtime.h>
#include <math.h>
#include <stdint.h>

#define TOKENS 100352      // 32 * 56 * 56  == 2048 windows * 49
#define D      384
#define D3     1152
#define DH     1536
#define NWIN   2048
#define HEADS  12

// -------- scratch (device globals; no allocation allowed) --------
__device__ float g_xw [(size_t)TOKENS * D];
__device__ float g_qkv[(size_t)TOKENS * D3];
__device__ float g_att[(size_t)TOKENS * D];
__device__ float g_x1 [(size_t)TOKENS * D];
__device__ float g_h  [(size_t)TOKENS * DH];
__device__ float g_bias[HEADS * 49 * 49];

// ================= CRPB bias table =================
__global__ void bias_kernel(const float* __restrict__ w1, const float* __restrict__ b1,
                            const float* __restrict__ w2, const float* __restrict__ b2) {
    int p = blockIdx.x;
    int i = p / 49, j = p % 49;
    float dr = (float)(i / 7 - j / 7);
    float dc = (float)(i % 7 - j % 7);
    float r0 = (dr == 0.f) ? 0.f : copysignf(log1pf(fabsf(dr)), dr);
    float r1 = (dc == 0.f) ? 0.f : copysignf(log1pf(fabsf(dc)), dc);
    __shared__ float hid[64];
    int t = threadIdx.x;
    if (t < 64) {
        float v = r0 * w1[t] + r1 * w1[64 + t] + b1[t];
        hid[t] = fmaxf(v, 0.f);
    }
    __syncthreads();
    if (t < HEADS) {
        float s = b2[t];
        #pragma unroll 8
        for (int k = 0; k < 64; k++) s += hid[k] * w2[k * HEADS + t];
        g_bias[t * 2401 + p] = s;
    }
}

// ================= LayerNorm (optionally fused shift+window-partition gather) =================
__global__ void ln_kernel(const float* __restrict__ x, const float* __restrict__ g,
                          const float* __restrict__ b, float* __restrict__ out, int mapped) {
    int r = blockIdx.x;
    int src = r;
    if (mapped) {
        int win = r / 49, pos = r % 49;
        int bb = win >> 6, wrem = win & 63;
        int wh = wrem >> 3, ww = wrem & 7;
        int rr = pos / 7, cc = pos % 7;
        int sh = (wh * 7 + rr + 3) % 56;
        int sw = (ww * 7 + cc + 3) % 56;
        src = bb * 3136 + sh * 56 + sw;
    }
    const float* xr = x + (size_t)src * D;
    int t = threadIdx.x;                       // 128 threads
    float v0 = xr[t], v1 = xr[t + 128], v2 = xr[t + 256];
    float s = v0 + v1 + v2;
    __shared__ float red[4];
    __shared__ float red2[4];
    #pragma unroll
    for (int o = 16; o > 0; o >>= 1) s += __shfl_down_sync(0xffffffffu, s, o);
    if ((t & 31) == 0) red[t >> 5] = s;
    __syncthreads();
    float mu = (red[0] + red[1] + red[2] + red[3]) * (1.f / 384.f);
    float d0 = v0 - mu, d1 = v1 - mu, d2 = v2 - mu;
    float q = d0 * d0 + d1 * d1 + d2 * d2;
    #pragma unroll
    for (int o = 16; o > 0; o >>= 1) q += __shfl_down_sync(0xffffffffu, q, o);
    if ((t & 31) == 0) red2[t >> 5] = q;
    __syncthreads();
    float var = (red2[0] + red2[1] + red2[2] + red2[3]) * (1.f / 384.f);
    float inv = rsqrtf(var + 1e-5f);
    float* orow = out + (size_t)r * D;
    orow[t]       = d0 * inv * g[t]       + b[t];
    orow[t + 128] = d1 * inv * g[t + 128] + b[t + 128];
    orow[t + 256] = d2 * inv * g[t + 256] + b[t + 256];
}

// ================= tf32 tensor-core GEMM, 3-stage cp.async pipeline =================
// C(MxN) = A(MxK) * W(KxN) + bias, fp32 in/out, tf32(raw) mma, fp32 accumulate.
// MODE 0: plain   MODE 1: gelu(exact)   MODE 2: proj scatter + residual   MODE 3: out + residual

#define APAD 20     // 16 k-floats + 4 pad  (conflict-free frag reads)
#define BPAD 132    // 128 n-floats + 4 pad
#define STAGES 3
#define A_STG (128 * APAD)
#define B_STG (16 * BPAD)
#define GEMM_SMEM ((STAGES * (A_STG + B_STG)) * sizeof(float))

__device__ __forceinline__ void mma_tf32(float* c, const unsigned* a, const unsigned* b) {
    asm volatile(
        "mma.sync.aligned.m16n8k8.row.col.f32.tf32.tf32.f32 "
        "{%0,%1,%2,%3}, {%4,%5,%6,%7}, {%8,%9}, {%0,%1,%2,%3};"
        : "+f"(c[0]), "+f"(c[1]), "+f"(c[2]), "+f"(c[3])
        : "r"(a[0]), "r"(a[1]), "r"(a[2]), "r"(a[3]), "r"(b[0]), "r"(b[1]));
}

__device__ __forceinline__ void cp16(void* dst_smem, const void* src_gmem) {
    uint32_t d = (uint32_t)__cvta_generic_to_shared(dst_smem);
    asm volatile("cp.async.ca.shared.global [%0], [%1], 16;\n" :: "r"(d), "l"(src_gmem));
}

template <int MODE>
__global__ __launch_bounds__(256, 2) void gemm_tc(
    const float* __restrict__ A, const float* __restrict__ W,
    const float* __restrict__ bias, float* __restrict__ C,
    int M, int N, int K, const float* __restrict__ add) {
    extern __shared__ float sm[];
    float* AsBase = sm;                      // [STAGES][128][APAD]
    float* BsBase = sm + STAGES * A_STG;     // [STAGES][16][BPAD]

    int tid = threadIdx.x;
    int lane = tid & 31, warp = tid >> 5;
    int bm = blockIdx.y * 128, bn = blockIdx.x * 128;
    int wm = (warp & 3) * 32, wn = (warp >> 2) * 64;
    int km = lane & 3;
    int mrow = lane >> 2;

    float acc[2][8][4];
    #pragma unroll
    for (int i = 0; i < 2; i++)
        #pragma unroll
        for (int j = 0; j < 8; j++)
            #pragma unroll
            for (int l = 0; l < 4; l++) acc[i][j][l] = 0.f;

    // staging coordinates (float4 granularity)
    int a_row0 = tid >> 2, a_kc = (tid & 3) * 4;        // rows tid>>2 and +64
    int b_kr0 = tid >> 6, b_nc = (tid & 63) * 2;        // hmm — use 512-float4 scheme below

    // A tile: 128x16 floats = 512 float4; thread handles f=tid, tid+256
    // B tile: 16x128 floats = 512 float4; same
    auto stage_copy = [&](int s, int k0) {
        float* as = AsBase + s * A_STG;
        float* bs = BsBase + s * B_STG;
        #pragma unroll
        for (int r = 0; r < 2; r++) {
            int f = tid + r * 256;
            int row = f >> 2, kc = (f & 3) * 4;
            cp16(as + row * APAD + kc, A + (size_t)(bm + row) * K + k0 + kc);
        }
        #pragma unroll
        for (int r = 0; r < 2; r++) {
            int g = tid + r * 256;
            int kr = g >> 5, nc = (g & 31) * 4;
            cp16(bs + kr * BPAD + nc, W + (size_t)(k0 + kr) * N + bn + nc);
        }
    };

    (void)a_row0; (void)a_kc; (void)b_kr0; (void)b_nc;

    stage_copy(0, 0);
    asm volatile("cp.async.commit_group;\n" ::);
    stage_copy(1, 16);
    asm volatile("cp.async.commit_group;\n" ::);

    int nit = K / 16;
    for (int it = 0; it < nit; it++) {
        asm volatile("cp.async.wait_group 1;\n" ::);
        __syncthreads();
        int nk = it + 2;
        if (nk < nit) stage_copy(nk % STAGES, nk * 16);
        asm volatile("cp.async.commit_group;\n" ::);

        const unsigned* as = (const unsigned*)(AsBase + (it % STAGES) * A_STG);
        const unsigned* bs = (const unsigned*)(BsBase + (it % STAGES) * B_STG);
        #pragma unroll
        for (int ks = 0; ks < 16; ks += 8) {
            unsigned af[2][4];
            #pragma unroll
            for (int mi = 0; mi < 2; mi++) {
                int m = wm + mi * 16 + mrow;
                af[mi][0] = as[(size_t)m * APAD + ks + km];
                af[mi][1] = as[(size_t)(m + 8) * APAD + ks + km];
                af[mi][2] = as[(size_t)m * APAD + ks + km + 4];
                af[mi][3] = as[(size_t)(m + 8) * APAD + ks + km + 4];
            }
            unsigned bf[8][2];
            #pragma unroll
            for (int ni = 0; ni < 8; ni++) {
                int n = wn + ni * 8 + mrow;
                bf[ni][0] = bs[(size_t)(ks + km) * BPAD + n];
                bf[ni][1] = bs[(size_t)(ks + km + 4) * BPAD + n];
            }
            #pragma unroll
            for (int mi = 0; mi < 2; mi++)
                #pragma unroll
                for (int ni = 0; ni < 8; ni++)
                    mma_tf32(acc[mi][ni], af[mi], bf[ni]);
        }
        __syncthreads();
    }

    // ---------- epilogue ----------
    int cbase = bn + wn + 2 * km;
    #pragma unroll
    for (int mi = 0; mi < 2; mi++) {
        #pragma unroll
        for (int half = 0; half < 2; half++) {
            int row = bm + wm + mi * 16 + mrow + half * 8;
            int dst = row;
            if (MODE == 2) {
                int win = row / 49, pos = row % 49;
                int bb = win >> 6, wrem = win & 63;
                int wh = wrem >> 3, ww = wrem & 7;
                int rr = pos / 7, cc = pos % 7;
                dst = bb * 3136 + ((wh * 7 + rr + 3) % 56) * 56 + ((ww * 7 + cc + 3) % 56);
            }
            float* cp = C + (size_t)dst * N;
            const float* ap = (MODE == 2 || MODE == 3) ? add + (size_t)dst * N : nullptr;
            #pragma unroll
            for (int ni = 0; ni < 8; ni++) {
                int col = cbase + ni * 8;
                float v0 = acc[mi][ni][half * 2 + 0] + bias[col];
                float v1 = acc[mi][ni][half * 2 + 1] + bias[col + 1];
                if (MODE == 1) {
                    v0 = 0.5f * v0 * (1.f + erff(v0 * 0.70710678118654752f));
                    v1 = 0.5f * v1 * (1.f + erff(v1 * 0.70710678118654752f));
                }
                if (MODE == 2 || MODE == 3) {
                    v0 += ap[col];
                    v1 += ap[col + 1];
                }
                float2 o = {v0, v1};
                *(float2*)(cp + col) = o;
            }
        }
    }
}

// ================= window attention: one block per (window, head) =================
__global__ void attn_kernel(const float* __restrict__ tau) {
    int blk = blockIdx.x;
    int win = blk / HEADS;
    int head = blk % HEADS;
    __shared__ float qs[49][32], ks[49][32], vs[49][32];
    __shared__ float S[49][52];
    __shared__ int lab[49];
    int t = threadIdx.x;                // 256
    int wrem = win & 63;
    int wh = wrem >> 3, ww = wrem & 7;
    if (t < 49) {
        int rr = t / 7, cc = t % 7;
        int h = wh * 7 + rr, w = ww * 7 + cc;
        int hs = (h < 49) ? 0 : ((h < 53) ? 1 : 2);
        int wsg = (w < 49) ? 0 : ((w < 53) ? 1 : 2);
        lab[t] = hs * 3 + wsg;
    }
    const float* base = g_qkv + (size_t)win * 49 * D3 + head * 32;
    for (int idx = t; idx < 49 * 32; idx += 256) {
        int i = idx >> 5, d = idx & 31;
        const float* p = base + (size_t)i * D3 + d;
        qs[i][d] = p[0];
        ks[i][d] = p[384];
        vs[i][d] = p[768];
    }
    __syncthreads();
    if (t < 98) {
        int i = (t < 49) ? t : (t - 49);
        float* row = (t < 49) ? qs[i] : ks[i];
        float ss = 0.f;
        #pragma unroll
        for (int d = 0; d < 32; d++) ss += row[d] * row[d];
        float inv = 1.f / fmaxf(sqrtf(ss), 1e-12f);
        #pragma unroll
        for (int d = 0; d < 32; d++) row[d] *= inv;
    }
    __syncthreads();
    float tauv = tau[head];
    const float* bh = g_bias + head * 2401;
    for (int idx = t; idx < 2401; idx += 256) {
        int i = idx / 49, j = idx % 49;
        float s = 0.f;
        #pragma unroll
        for (int d = 0; d < 32; d++) s += qs[i][d] * ks[j][d];
        s = s * tauv + bh[idx];
        if (lab[i] != lab[j]) s -= 100.f;
        S[i][j] = s;
    }
    __syncthreads();
    if (t < 49) {
        float m = -1e30f;
        #pragma unroll 7
        for (int j = 0; j < 49; j++) m = fmaxf(m, S[t][j]);
        float sum = 0.f;
        #pragma unroll 7
        for (int j = 0; j < 49; j++) { float e = __expf(S[t][j] - m); S[t][j] = e; sum += e; }
        float inv = 1.f / sum;
        #pragma unroll 7
        for (int j = 0; j < 49; j++) S[t][j] *= inv;
    }
    __syncthreads();
    float* outbase = g_att + (size_t)win * 49 * D + head * 32;
    for (int idx = t; idx < 49 * 32; idx += 256) {
        int i = idx >> 5, d = idx & 31;
        float s = 0.f;
        #pragma unroll 7
        for (int j = 0; j < 49; j++) s += S[i][j] * vs[j][d];
        outbase[(size_t)i * D + d] = s;
    }
}

// ================= launch =================
extern "C" void kernel_launch(void* const* d_in, const int* in_sizes, int n_in,
                              void* d_out, int out_size) {
    const float* x       = (const float*)d_in[0];
    const float* n1g     = (const float*)d_in[1];
    const float* n1b     = (const float*)d_in[2];
    const float* qkv_w   = (const float*)d_in[3];
    const float* qkv_b   = (const float*)d_in[4];
    const float* tau     = (const float*)d_in[5];
    const float* proj_w  = (const float*)d_in[6];
    const float* proj_b  = (const float*)d_in[7];
    const float* crpb_w1 = (const float*)d_in[8];
    const float* crpb_b1 = (const float*)d_in[9];
    const float* crpb_w2 = (const float*)d_in[10];
    const float* crpb_b2 = (const float*)d_in[11];
    const float* n2g     = (const float*)d_in[12];
    const float* n2b     = (const float*)d_in[13];
    const float* mlp_w1  = (const float*)d_in[14];
    const float* mlp_b1  = (const float*)d_in[15];
    const float* mlp_w2  = (const float*)d_in[16];
    const float* mlp_b2  = (const float*)d_in[17];
    float* out = (float*)d_out;

    float *xw, *qkv, *att, *x1, *hbuf;
    cudaGetSymbolAddress((void**)&xw,  g_xw);
    cudaGetSymbolAddress((void**)&qkv, g_qkv);
    cudaGetSymbolAddress((void**)&att, g_att);
    cudaGetSymbolAddress((void**)&x1,  g_x1);
    cudaGetSymbolAddress((void**)&hbuf, g_h);

    static int smem_set = 0;
    if (!smem_set) {
        cudaFuncSetAttribute(gemm_tc<0>, cudaFuncAttributeMaxDynamicSharedMemorySize, (int)GEMM_SMEM);
        cudaFuncSetAttribute(gemm_tc<1>, cudaFuncAttributeMaxDynamicSharedMemorySize, (int)GEMM_SMEM);
        cudaFuncSetAttribute(gemm_tc<2>, cudaFuncAttributeMaxDynamicSharedMemorySize, (int)GEMM_SMEM);
        cudaFuncSetAttribute(gemm_tc<3>, cudaFuncAttributeMaxDynamicSharedMemorySize, (int)GEMM_SMEM);
        smem_set = 1;
    }

    const int MB = TOKENS / 128;   // 784

    bias_kernel<<<2401, 64>>>(crpb_w1, crpb_b1, crpb_w2, crpb_b2);
    ln_kernel<<<TOKENS, 128>>>(x, n1g, n1b, xw, 1);
    gemm_tc<0><<<dim3(D3 / 128, MB), 256, GEMM_SMEM>>>(xw, qkv_w, qkv_b, qkv, TOKENS, D3, D, nullptr);
    attn_kernel<<<NWIN * HEADS, 256>>>(tau);
    gemm_tc<2><<<dim3(D / 128, MB), 256, GEMM_SMEM>>>(att, proj_w, proj_b, x1, TOKENS, D, D, x);
    ln_kernel<<<TOKENS, 128>>>(x1, n2g, n2b, xw, 0);
    gemm_tc<1><<<dim3(DH / 128, MB), 256, GEMM_SMEM>>>(xw, mlp_w1, mlp_b1, hbuf, TOKENS, DH, D, nullptr);
    gemm_tc<3><<<dim3(D / 128, MB), 256, GEMM_SMEM>>>(hbuf, mlp_w2, mlp_b2, out, TOKENS, D, DH, x1);
}

// round 5
// speedup vs baseline: 2.2350x; 1.0319x over previous
#include <cuda_runtime.h>
#include <math.h>
#include <stdint.h>

#define TOKENS 100352      // 32 * 56 * 56  == 2048 windows * 49
#define D      384
#define D3     1152
#define DH     1536
#define NWIN   2048
#define HEADS  12

// -------- scratch (device globals; no allocation allowed) --------
__device__ float g_xw [(size_t)TOKENS * D];
__device__ float g_qkv[(size_t)TOKENS * D3];
__device__ float g_att[(size_t)TOKENS * D];
__device__ float g_x1 [(size_t)TOKENS * D];
__device__ float g_h  [(size_t)TOKENS * DH];
__device__ float g_bias[HEADS * 49 * 49];
// transposed weights [N][K]
__device__ float g_wt_qkv[D3 * D];
__device__ float g_wt_proj[D * D];
__device__ float g_wt_m1[DH * D];
__device__ float g_wt_m2[D * DH];

// ================= weight transpose: Wt[n][k] = W[k][n] =================
__global__ void transpose_kernel(const float* __restrict__ W, float* __restrict__ Wt,
                                 int K, int N) {
    __shared__ float tile[32][33];
    int n0 = blockIdx.x * 32, k0 = blockIdx.y * 32;
    int tx = threadIdx.x, ty = threadIdx.y;   // 32 x 8
    #pragma unroll
    for (int i = 0; i < 32; i += 8) tile[ty + i][tx] = W[(size_t)(k0 + ty + i) * N + n0 + tx];
    __syncthreads();
    #pragma unroll
    for (int i = 0; i < 32; i += 8) Wt[(size_t)(n0 + ty + i) * K + k0 + tx] = tile[tx][ty + i];
}

// ================= CRPB bias table =================
__global__ void bias_kernel(const float* __restrict__ w1, const float* __restrict__ b1,
                            const float* __restrict__ w2, const float* __restrict__ b2) {
    int p = blockIdx.x;
    int i = p / 49, j = p % 49;
    float dr = (float)(i / 7 - j / 7);
    float dc = (float)(i % 7 - j % 7);
    float r0 = (dr == 0.f) ? 0.f : copysignf(log1pf(fabsf(dr)), dr);
    float r1 = (dc == 0.f) ? 0.f : copysignf(log1pf(fabsf(dc)), dc);
    __shared__ float hid[64];
    int t = threadIdx.x;
    if (t < 64) {
        float v = r0 * w1[t] + r1 * w1[64 + t] + b1[t];
        hid[t] = fmaxf(v, 0.f);
    }
    __syncthreads();
    if (t < HEADS) {
        float s = b2[t];
        #pragma unroll 8
        for (int k = 0; k < 64; k++) s += hid[k] * w2[k * HEADS + t];
        g_bias[t * 2401 + p] = s;
    }
}

// ================= LayerNorm (optionally fused shift+window gather) =================
__global__ void ln_kernel(const float* __restrict__ x, const float* __restrict__ g,
                          const float* __restrict__ b, float* __restrict__ out, int mapped) {
    int r = blockIdx.x;
    int src = r;
    if (mapped) {
        int win = r / 49, pos = r % 49;
        int bb = win >> 6, wrem = win & 63;
        int wh = wrem >> 3, ww = wrem & 7;
        int rr = pos / 7, cc = pos % 7;
        int sh = (wh * 7 + rr + 3) % 56;
        int sw = (ww * 7 + cc + 3) % 56;
        src = bb * 3136 + sh * 56 + sw;
    }
    const float* xr = x + (size_t)src * D;
    int t = threadIdx.x;                       // 128 threads
    float v0 = xr[t], v1 = xr[t + 128], v2 = xr[t + 256];
    float s = v0 + v1 + v2;
    __shared__ float red[4];
    __shared__ float red2[4];
    #pragma unroll
    for (int o = 16; o > 0; o >>= 1) s += __shfl_down_sync(0xffffffffu, s, o);
    if ((t & 31) == 0) red[t >> 5] = s;
    __syncthreads();
    float mu = (red[0] + red[1] + red[2] + red[3]) * (1.f / 384.f);
    float d0 = v0 - mu, d1 = v1 - mu, d2 = v2 - mu;
    float q = d0 * d0 + d1 * d1 + d2 * d2;
    #pragma unroll
    for (int o = 16; o > 0; o >>= 1) q += __shfl_down_sync(0xffffffffu, q, o);
    if ((t & 31) == 0) red2[t >> 5] = q;
    __syncthreads();
    float var = (red2[0] + red2[1] + red2[2] + red2[3]) * (1.f / 384.f);
    float inv = rsqrtf(var + 1e-5f);
    float* orow = out + (size_t)r * D;
    orow[t]       = d0 * inv * g[t]       + b[t];
    orow[t + 128] = d1 * inv * g[t + 128] + b[t + 128];
    orow[t + 256] = d2 * inv * g[t + 256] + b[t + 256];
}

// ================= tf32 tensor-core GEMM, 256x128 tile, 64x64 per warp =================
// C(MxN) = A(MxK) * Wt(NxK)^T + bias, fp32 in/out, tf32(raw-bits) mma, fp32 accumulate.
// Both A and B staged [row][K16 + 4pad] for conflict-free fragment reads.
// MODE 0: plain  MODE 1: gelu(exact)  MODE 2: scatter+residual  MODE 3: +residual

#define RPAD 20
#define STAGES 3
#define A_STG (256 * RPAD)
#define B_STG (128 * RPAD)
#define GEMM_SMEM ((STAGES * (A_STG + B_STG)) * sizeof(float))

__device__ __forceinline__ void mma_tf32(float* c, const unsigned* a, const unsigned* b) {
    asm volatile(
        "mma.sync.aligned.m16n8k8.row.col.f32.tf32.tf32.f32 "
        "{%0,%1,%2,%3}, {%4,%5,%6,%7}, {%8,%9}, {%0,%1,%2,%3};"
        : "+f"(c[0]), "+f"(c[1]), "+f"(c[2]), "+f"(c[3])
        : "r"(a[0]), "r"(a[1]), "r"(a[2]), "r"(a[3]), "r"(b[0]), "r"(b[1]));
}

__device__ __forceinline__ void cp16(void* dst_smem, const void* src_gmem) {
    uint32_t d = (uint32_t)__cvta_generic_to_shared(dst_smem);
    asm volatile("cp.async.cg.shared.global [%0], [%1], 16;\n" :: "r"(d), "l"(src_gmem));
}

template <int MODE>
__global__ __launch_bounds__(256, 1) void gemm_tc(
    const float* __restrict__ A, const float* __restrict__ Wt,
    const float* __restrict__ bias, float* __restrict__ C,
    int K, int N, const float* __restrict__ add) {
    extern __shared__ float sm[];
    float* AsBase = sm;                      // [STAGES][256][RPAD]
    float* BsBase = sm + STAGES * A_STG;     // [STAGES][128][RPAD]

    int tid = threadIdx.x;
    int lane = tid & 31, warp = tid >> 5;
    int bm = blockIdx.y * 256, bn = blockIdx.x * 128;
    int wm = (warp & 3) * 64, wn = (warp >> 2) * 64;
    int km = lane & 3;
    int mrow = lane >> 2;

    float acc[4][8][4];
    #pragma unroll
    for (int i = 0; i < 4; i++)
        #pragma unroll
        for (int j = 0; j < 8; j++)
            #pragma unroll
            for (int l = 0; l < 4; l++) acc[i][j][l] = 0.f;

    auto stage_copy = [&](int s, int k0) {
        float* as = AsBase + s * A_STG;
        float* bs = BsBase + s * B_STG;
        #pragma unroll
        for (int r = 0; r < 4; r++) {            // A: 256 rows x 16 k = 1024 float4
            int f = tid + r * 256;
            int row = f >> 2, kc = (f & 3) * 4;
            cp16(as + row * RPAD + kc, A + (size_t)(bm + row) * K + k0 + kc);
        }
        #pragma unroll
        for (int r = 0; r < 2; r++) {            // B: 128 rows x 16 k = 512 float4
            int g = tid + r * 256;
            int row = g >> 2, kc = (g & 3) * 4;
            cp16(bs + row * RPAD + kc, Wt + (size_t)(bn + row) * K + k0 + kc);
        }
    };

    stage_copy(0, 0);
    asm volatile("cp.async.commit_group;\n" ::);
    stage_copy(1, 16);
    asm volatile("cp.async.commit_group;\n" ::);

    int nit = K / 16;
    for (int it = 0; it < nit; it++) {
        asm volatile("cp.async.wait_group 1;\n" ::);
        __syncthreads();
        int nk = it + 2;
        if (nk < nit) stage_copy(nk % STAGES, nk * 16);
        asm volatile("cp.async.commit_group;\n" ::);

        const unsigned* as = (const unsigned*)(AsBase + (it % STAGES) * A_STG);
        const unsigned* bs = (const unsigned*)(BsBase + (it % STAGES) * B_STG);
        #pragma unroll
        for (int ks = 0; ks < 16; ks += 8) {
            unsigned af[4][4];
            #pragma unroll
            for (int mi = 0; mi < 4; mi++) {
                int m = wm + mi * 16 + mrow;
                af[mi][0] = as[(unsigned)m * RPAD + ks + km];
                af[mi][1] = as[(unsigned)(m + 8) * RPAD + ks + km];
                af[mi][2] = as[(unsigned)m * RPAD + ks + km + 4];
                af[mi][3] = as[(unsigned)(m + 8) * RPAD + ks + km + 4];
            }
            unsigned bf[8][2];
            #pragma unroll
            for (int ni = 0; ni < 8; ni++) {
                int n = wn + ni * 8 + mrow;
                bf[ni][0] = bs[(unsigned)n * RPAD + ks + km];
                bf[ni][1] = bs[(unsigned)n * RPAD + ks + km + 4];
            }
            #pragma unroll
            for (int mi = 0; mi < 4; mi++)
                #pragma unroll
                for (int ni = 0; ni < 8; ni++)
                    mma_tf32(acc[mi][ni], af[mi], bf[ni]);
        }
        __syncthreads();
    }

    // ---------- epilogue ----------
    int cbase = bn + wn + 2 * km;
    #pragma unroll
    for (int mi = 0; mi < 4; mi++) {
        #pragma unroll
        for (int half = 0; half < 2; half++) {
            int row = bm + wm + mi * 16 + mrow + half * 8;
            int dst = row;
            if (MODE == 2) {
                int win = row / 49, pos = row % 49;
                int bb = win >> 6, wrem = win & 63;
                int wh = wrem >> 3, ww = wrem & 7;
                int rr = pos / 7, cc = pos % 7;
                dst = bb * 3136 + ((wh * 7 + rr + 3) % 56) * 56 + ((ww * 7 + cc + 3) % 56);
            }
            float* cp = C + (size_t)dst * N;
            const float* ap = (MODE == 2 || MODE == 3) ? add + (size_t)dst * N : nullptr;
            #pragma unroll
            for (int ni = 0; ni < 8; ni++) {
                int col = cbase + ni * 8;
                float v0 = acc[mi][ni][half * 2 + 0] + bias[col];
                float v1 = acc[mi][ni][half * 2 + 1] + bias[col + 1];
                if (MODE == 1) {
                    v0 = 0.5f * v0 * (1.f + erff(v0 * 0.70710678118654752f));
                    v1 = 0.5f * v1 * (1.f + erff(v1 * 0.70710678118654752f));
                }
                if (MODE == 2 || MODE == 3) {
                    v0 += ap[col];
                    v1 += ap[col + 1];
                }
                float2 o = {v0, v1};
                *(float2*)(cp + col) = o;
            }
        }
    }
}

// ================= window attention: one block per (window, head) =================
__global__ void attn_kernel(const float* __restrict__ tau) {
    int blk = blockIdx.x;
    int win = blk / HEADS;
    int head = blk % HEADS;
    __shared__ float qs[49][32], ks[49][32], vs[49][32];
    __shared__ float S[49][52];
    __shared__ int lab[49];
    int t = threadIdx.x;                // 256
    int wrem = win & 63;
    int wh = wrem >> 3, ww = wrem & 7;
    if (t < 49) {
        int rr = t / 7, cc = t % 7;
        int h = wh * 7 + rr, w = ww * 7 + cc;
        int hs = (h < 49) ? 0 : ((h < 53) ? 1 : 2);
        int wsg = (w < 49) ? 0 : ((w < 53) ? 1 : 2);
        lab[t] = hs * 3 + wsg;
    }
    const float* base = g_qkv + (size_t)win * 49 * D3 + head * 32;
    for (int idx = t; idx < 49 * 32; idx += 256) {
        int i = idx >> 5, d = idx & 31;
        const float* p = base + (size_t)i * D3 + d;
        qs[i][d] = p[0];
        ks[i][d] = p[384];
        vs[i][d] = p[768];
    }
    __syncthreads();
    if (t < 98) {
        int i = (t < 49) ? t : (t - 49);
        float* row = (t < 49) ? qs[i] : ks[i];
        float ss = 0.f;
        #pragma unroll
        for (int d = 0; d < 32; d++) ss += row[d] * row[d];
        float inv = 1.f / fmaxf(sqrtf(ss), 1e-12f);
        #pragma unroll
        for (int d = 0; d < 32; d++) row[d] *= inv;
    }
    __syncthreads();
    float tauv = tau[head];
    const float* bh = g_bias + head * 2401;
    for (int idx = t; idx < 2401; idx += 256) {
        int i = idx / 49, j = idx % 49;
        float s = 0.f;
        #pragma unroll
        for (int d = 0; d < 32; d++) s += qs[i][d] * ks[j][d];
        s = s * tauv + bh[idx];
        if (lab[i] != lab[j]) s -= 100.f;
        S[i][j] = s;
    }
    __syncthreads();
    if (t < 49) {
        float m = -1e30f;
        #pragma unroll 7
        for (int j = 0; j < 49; j++) m = fmaxf(m, S[t][j]);
        float sum = 0.f;
        #pragma unroll 7
        for (int j = 0; j < 49; j++) { float e = __expf(S[t][j] - m); S[t][j] = e; sum += e; }
        float inv = 1.f / sum;
        #pragma unroll 7
        for (int j = 0; j < 49; j++) S[t][j] *= inv;
    }
    __syncthreads();
    float* outbase = g_att + (size_t)win * 49 * D + head * 32;
    for (int idx = t; idx < 49 * 32; idx += 256) {
        int i = idx >> 5, d = idx & 31;
        float s = 0.f;
        #pragma unroll 7
        for (int j = 0; j < 49; j++) s += S[i][j] * vs[j][d];
        outbase[(size_t)i * D + d] = s;
    }
}

// ================= launch =================
extern "C" void kernel_launch(void* const* d_in, const int* in_sizes, int n_in,
                              void* d_out, int out_size) {
    const float* x       = (const float*)d_in[0];
    const float* n1g     = (const float*)d_in[1];
    const float* n1b     = (const float*)d_in[2];
    const float* qkv_w   = (const float*)d_in[3];
    const float* qkv_b   = (const float*)d_in[4];
    const float* tau     = (const float*)d_in[5];
    const float* proj_w  = (const float*)d_in[6];
    const float* proj_b  = (const float*)d_in[7];
    const float* crpb_w1 = (const float*)d_in[8];
    const float* crpb_b1 = (const float*)d_in[9];
    const float* crpb_w2 = (const float*)d_in[10];
    const float* crpb_b2 = (const float*)d_in[11];
    const float* n2g     = (const float*)d_in[12];
    const float* n2b     = (const float*)d_in[13];
    const float* mlp_w1  = (const float*)d_in[14];
    const float* mlp_b1  = (const float*)d_in[15];
    const float* mlp_w2  = (const float*)d_in[16];
    const float* mlp_b2  = (const float*)d_in[17];
    float* out = (float*)d_out;

    float *xw, *qkv, *att, *x1, *hbuf;
    float *wtq, *wtp, *wt1, *wt2;
    cudaGetSymbolAddress((void**)&xw,  g_xw);
    cudaGetSymbolAddress((void**)&qkv, g_qkv);
    cudaGetSymbolAddress((void**)&att, g_att);
    cudaGetSymbolAddress((void**)&x1,  g_x1);
    cudaGetSymbolAddress((void**)&hbuf, g_h);
    cudaGetSymbolAddress((void**)&wtq, g_wt_qkv);
    cudaGetSymbolAddress((void**)&wtp, g_wt_proj);
    cudaGetSymbolAddress((void**)&wt1, g_wt_m1);
    cudaGetSymbolAddress((void**)&wt2, g_wt_m2);

    static int attr_set = 0;
    if (!attr_set) {
        cudaFuncSetAttribute(gemm_tc<0>, cudaFuncAttributeMaxDynamicSharedMemorySize, (int)GEMM_SMEM);
        cudaFuncSetAttribute(gemm_tc<1>, cudaFuncAttributeMaxDynamicSharedMemorySize, (int)GEMM_SMEM);
        cudaFuncSetAttribute(gemm_tc<2>, cudaFuncAttributeMaxDynamicSharedMemorySize, (int)GEMM_SMEM);
        cudaFuncSetAttribute(gemm_tc<3>, cudaFuncAttributeMaxDynamicSharedMemorySize, (int)GEMM_SMEM);
        attr_set = 1;
    }

    const int MB = TOKENS / 256;   // 392
    dim3 tb(32, 8);

    transpose_kernel<<<dim3(D3 / 32, D / 32), tb>>>(qkv_w, wtq, D, D3);
    transpose_kernel<<<dim3(D / 32, D / 32), tb>>>(proj_w, wtp, D, D);
    transpose_kernel<<<dim3(DH / 32, D / 32), tb>>>(mlp_w1, wt1, D, DH);
    transpose_kernel<<<dim3(D / 32, DH / 32), tb>>>(mlp_w2, wt2, DH, D);
    bias_kernel<<<2401, 64>>>(crpb_w1, crpb_b1, crpb_w2, crpb_b2);

    ln_kernel<<<TOKENS, 128>>>(x, n1g, n1b, xw, 1);
    gemm_tc<0><<<dim3(D3 / 128, MB), 256, GEMM_SMEM>>>(xw, wtq, qkv_b, qkv, D, D3, nullptr);
    attn_kernel<<<NWIN * HEADS, 256>>>(tau);
    gemm_tc<2><<<dim3(D / 128, MB), 256, GEMM_SMEM>>>(att, wtp, proj_b, x1, D, D, x);
    ln_kernel<<<TOKENS, 128>>>(x1, n2g, n2b, xw, 0);
    gemm_tc<1><<<dim3(DH / 128, MB), 256, GEMM_SMEM>>>(xw, wt1, mlp_b1, hbuf, D, DH, nullptr);
    gemm_tc<3><<<dim3(D / 128, MB), 256, GEMM_SMEM>>>(hbuf, wt2, mlp_b2, out, DH, x1 == nullptr ? D : D, x1);
}

// round 6
// speedup vs baseline: 2.5797x; 1.1542x over previous
#include <cuda_runtime.h>
#include <cuda_fp16.h>
#include <math.h>
#include <stdint.h>

#define TOKENS 100352      // 32 * 56 * 56  == 2048 windows * 49
#define D      384
#define D3     1152
#define DH     1536
#define NWIN   2048
#define HEADS  12

// -------- scratch (device globals; no allocation allowed) --------
__device__ __half g_xw [(size_t)TOKENS * D];     // LN out (half, GEMM A operand)
__device__ float  g_qkv[(size_t)TOKENS * D3];    // qkv (fp32 for attention math)
__device__ __half g_att[(size_t)TOKENS * D];     // attention out (half)
__device__ float  g_x1 [(size_t)TOKENS * D];     // proj + residual (fp32)
__device__ __half g_h  [(size_t)TOKENS * DH];    // mlp hidden (half)
__device__ float  g_bias[HEADS * 49 * 49];
// transposed + fp16 weights [N][K]
__device__ __half g_wt_qkv[D3 * D];
__device__ __half g_wt_proj[D * D];
__device__ __half g_wt_m1[DH * D];
__device__ __half g_wt_m2[D * DH];

// ================= weight transpose + fp16 convert: Wt[n][k] = W[k][n] =================
__global__ void transpose_kernel(const float* __restrict__ W, __half* __restrict__ Wt,
                                 int K, int N) {
    __shared__ float tile[32][33];
    int n0 = blockIdx.x * 32, k0 = blockIdx.y * 32;
    int tx = threadIdx.x, ty = threadIdx.y;   // 32 x 8
    #pragma unroll
    for (int i = 0; i < 32; i += 8) tile[ty + i][tx] = W[(size_t)(k0 + ty + i) * N + n0 + tx];
    __syncthreads();
    #pragma unroll
    for (int i = 0; i < 32; i += 8)
        Wt[(size_t)(n0 + ty + i) * K + k0 + tx] = __float2half(tile[tx][ty + i]);
}

// ================= CRPB bias table =================
__global__ void bias_kernel(const float* __restrict__ w1, const float* __restrict__ b1,
                            const float* __restrict__ w2, const float* __restrict__ b2) {
    int p = blockIdx.x;
    int i = p / 49, j = p % 49;
    float dr = (float)(i / 7 - j / 7);
    float dc = (float)(i % 7 - j % 7);
    float r0 = (dr == 0.f) ? 0.f : copysignf(log1pf(fabsf(dr)), dr);
    float r1 = (dc == 0.f) ? 0.f : copysignf(log1pf(fabsf(dc)), dc);
    __shared__ float hid[64];
    int t = threadIdx.x;
    if (t < 64) {
        float v = r0 * w1[t] + r1 * w1[64 + t] + b1[t];
        hid[t] = fmaxf(v, 0.f);
    }
    __syncthreads();
    if (t < HEADS) {
        float s = b2[t];
        #pragma unroll 8
        for (int k = 0; k < 64; k++) s += hid[k] * w2[k * HEADS + t];
        g_bias[t * 2401 + p] = s;
    }
}

// ================= LayerNorm -> half (optionally fused shift+window gather) =================
__global__ void ln_kernel(const float* __restrict__ x, const float* __restrict__ g,
                          const float* __restrict__ b, __half* __restrict__ out, int mapped) {
    int r = blockIdx.x;
    int src = r;
    if (mapped) {
        int win = r / 49, pos = r % 49;
        int bb = win >> 6, wrem = win & 63;
        int wh = wrem >> 3, ww = wrem & 7;
        int rr = pos / 7, cc = pos % 7;
        int sh = (wh * 7 + rr + 3) % 56;
        int sw = (ww * 7 + cc + 3) % 56;
        src = bb * 3136 + sh * 56 + sw;
    }
    const float* xr = x + (size_t)src * D;
    int t = threadIdx.x;                       // 128 threads
    float v0 = xr[t], v1 = xr[t + 128], v2 = xr[t + 256];
    float s = v0 + v1 + v2;
    __shared__ float red[4];
    __shared__ float red2[4];
    #pragma unroll
    for (int o = 16; o > 0; o >>= 1) s += __shfl_down_sync(0xffffffffu, s, o);
    if ((t & 31) == 0) red[t >> 5] = s;
    __syncthreads();
    float mu = (red[0] + red[1] + red[2] + red[3]) * (1.f / 384.f);
    float d0 = v0 - mu, d1 = v1 - mu, d2 = v2 - mu;
    float q = d0 * d0 + d1 * d1 + d2 * d2;
    #pragma unroll
    for (int o = 16; o > 0; o >>= 1) q += __shfl_down_sync(0xffffffffu, q, o);
    if ((t & 31) == 0) red2[t >> 5] = q;
    __syncthreads();
    float var = (red2[0] + red2[1] + red2[2] + red2[3]) * (1.f / 384.f);
    float inv = rsqrtf(var + 1e-5f);
    __half* orow = out + (size_t)r * D;
    orow[t]       = __float2half(d0 * inv * g[t]       + b[t]);
    orow[t + 128] = __float2half(d1 * inv * g[t + 128] + b[t + 128]);
    orow[t + 256] = __float2half(d2 * inv * g[t + 256] + b[t + 256]);
}

// ================= fp16 tensor-core GEMM, 256x128 tile, 64x64 per warp =================
// C(MxN) = A(MxK) * Wt(NxK)^T + bias.  A,Wt half; accumulate fp32.
// SMEM rows: 16 halves (8 words) + 4 pad words; stride 12 words is a perfect
// mod-32 bank permutation for the (8 rows x 4 words) fragment access.
// MODE 0: plain->f32   MODE 1: gelu->half   MODE 2: scatter+residual->f32   MODE 3: +residual->f32

#define RPAD 12                 // words per smem row
#define STAGES 3
#define A_STG (256 * RPAD)      // words
#define B_STG (128 * RPAD)
#define GEMM_SMEM ((STAGES * (A_STG + B_STG)) * 4)

__device__ __forceinline__ void mma_f16(float* c, const unsigned* a, const unsigned* b) {
    asm volatile(
        "mma.sync.aligned.m16n8k16.row.col.f32.f16.f16.f32 "
        "{%0,%1,%2,%3}, {%4,%5,%6,%7}, {%8,%9}, {%0,%1,%2,%3};"
        : "+f"(c[0]), "+f"(c[1]), "+f"(c[2]), "+f"(c[3])
        : "r"(a[0]), "r"(a[1]), "r"(a[2]), "r"(a[3]), "r"(b[0]), "r"(b[1]));
}

__device__ __forceinline__ void cp16(void* dst_smem, const void* src_gmem) {
    uint32_t d = (uint32_t)__cvta_generic_to_shared(dst_smem);
    asm volatile("cp.async.ca.shared.global [%0], [%1], 16;\n" :: "r"(d), "l"(src_gmem));
}

template <int MODE, typename OutT>
__global__ __launch_bounds__(256, 1) void gemm_tc(
    const __half* __restrict__ A, const __half* __restrict__ Wt,
    const float* __restrict__ bias, OutT* __restrict__ C,
    int K, int N, const float* __restrict__ add) {
    extern __shared__ unsigned sm[];
    unsigned* AsBase = sm;                      // [STAGES][256][RPAD] words
    unsigned* BsBase = sm + STAGES * A_STG;     // [STAGES][128][RPAD]

    int tid = threadIdx.x;
    int lane = tid & 31, warp = tid >> 5;
    int bm = blockIdx.y * 256, bn = blockIdx.x * 128;
    int wm = (warp & 3) * 64, wn = (warp >> 2) * 64;
    int km = lane & 3;
    int mrow = lane >> 2;

    float acc[4][8][4];
    #pragma unroll
    for (int i = 0; i < 4; i++)
        #pragma unroll
        for (int j = 0; j < 8; j++)
            #pragma unroll
            for (int l = 0; l < 4; l++) acc[i][j][l] = 0.f;

    // A tile: 256 rows x 16 halves = 512 x 16B chunks; B: 128 rows -> 256 chunks
    auto stage_copy = [&](int s, int k0) {
        unsigned* as = AsBase + s * A_STG;
        unsigned* bs = BsBase + s * B_STG;
        #pragma unroll
        for (int r = 0; r < 2; r++) {
            int c = tid + r * 256;
            int row = c >> 1, half16 = (c & 1);
            cp16(as + row * RPAD + half16 * 4,
                 A + (size_t)(bm + row) * K + k0 + half16 * 8);
        }
        {
            int c = tid;
            int row = c >> 1, half16 = (c & 1);
            cp16(bs + row * RPAD + half16 * 4,
                 Wt + (size_t)(bn + row) * K + k0 + half16 * 8);
        }
    };

    stage_copy(0, 0);
    asm volatile("cp.async.commit_group;\n" ::);
    stage_copy(1, 16);
    asm volatile("cp.async.commit_group;\n" ::);

    int nit = K / 16;
    for (int it = 0; it < nit; it++) {
        asm volatile("cp.async.wait_group 1;\n" ::);
        __syncthreads();
        int nk = it + 2;
        if (nk < nit) stage_copy(nk % STAGES, nk * 16);
        asm volatile("cp.async.commit_group;\n" ::);

        const unsigned* as = AsBase + (it % STAGES) * A_STG;
        const unsigned* bs = BsBase + (it % STAGES) * B_STG;
        unsigned af[4][4];
        #pragma unroll
        for (int mi = 0; mi < 4; mi++) {
            int m = wm + mi * 16 + mrow;
            af[mi][0] = as[(unsigned)m * RPAD + km];
            af[mi][1] = as[(unsigned)(m + 8) * RPAD + km];
            af[mi][2] = as[(unsigned)m * RPAD + km + 4];
            af[mi][3] = as[(unsigned)(m + 8) * RPAD + km + 4];
        }
        unsigned bf[8][2];
        #pragma unroll
        for (int ni = 0; ni < 8; ni++) {
            int n = wn + ni * 8 + mrow;
            bf[ni][0] = bs[(unsigned)n * RPAD + km];
            bf[ni][1] = bs[(unsigned)n * RPAD + km + 4];
        }
        #pragma unroll
        for (int mi = 0; mi < 4; mi++)
            #pragma unroll
            for (int ni = 0; ni < 8; ni++)
                mma_f16(acc[mi][ni], af[mi], bf[ni]);
        __syncthreads();
    }

    // ---------- epilogue ----------
    int cbase = bn + wn + 2 * km;
    #pragma unroll
    for (int mi = 0; mi < 4; mi++) {
        #pragma unroll
        for (int half = 0; half < 2; half++) {
            int row = bm + wm + mi * 16 + mrow + half * 8;
            int dst = row;
            if (MODE == 2) {
                int win = row / 49, pos = row % 49;
                int bb = win >> 6, wrem = win & 63;
                int wh = wrem >> 3, ww = wrem & 7;
                int rr = pos / 7, cc = pos % 7;
                dst = bb * 3136 + ((wh * 7 + rr + 3) % 56) * 56 + ((ww * 7 + cc + 3) % 56);
            }
            OutT* cp = C + (size_t)dst * N;
            const float* ap = (MODE == 2 || MODE == 3) ? add + (size_t)dst * N : nullptr;
            #pragma unroll
            for (int ni = 0; ni < 8; ni++) {
                int col = cbase + ni * 8;
                float v0 = acc[mi][ni][half * 2 + 0] + bias[col];
                float v1 = acc[mi][ni][half * 2 + 1] + bias[col + 1];
                if (MODE == 1) {
                    v0 = 0.5f * v0 * (1.f + erff(v0 * 0.70710678118654752f));
                    v1 = 0.5f * v1 * (1.f + erff(v1 * 0.70710678118654752f));
                }
                if (MODE == 2 || MODE == 3) {
                    v0 += ap[col];
                    v1 += ap[col + 1];
                }
                if (sizeof(OutT) == 2) {
                    __half2 o = __floats2half2_rn(v0, v1);
                    *(__half2*)((__half*)cp + col) = o;
                } else {
                    float2 o = {v0, v1};
                    *(float2*)((float*)cp + col) = o;
                }
            }
        }
    }
}

// ================= window attention: one block per (window, head) =================
__global__ void attn_kernel(const float* __restrict__ tau) {
    int blk = blockIdx.x;
    int win = blk / HEADS;
    int head = blk % HEADS;
    __shared__ float qs[49][32], ks[49][32], vs[49][32];
    __shared__ float S[49][52];
    __shared__ int lab[49];
    int t = threadIdx.x;                // 256
    int wrem = win & 63;
    int wh = wrem >> 3, ww = wrem & 7;
    if (t < 49) {
        int rr = t / 7, cc = t % 7;
        int h = wh * 7 + rr, w = ww * 7 + cc;
        int hs = (h < 49) ? 0 : ((h < 53) ? 1 : 2);
        int wsg = (w < 49) ? 0 : ((w < 53) ? 1 : 2);
        lab[t] = hs * 3 + wsg;
    }
    const float* base = g_qkv + (size_t)win * 49 * D3 + head * 32;
    for (int idx = t; idx < 49 * 32; idx += 256) {
        int i = idx >> 5, d = idx & 31;
        const float* p = base + (size_t)i * D3 + d;
        qs[i][d] = p[0];
        ks[i][d] = p[384];
        vs[i][d] = p[768];
    }
    __syncthreads();
    if (t < 98) {
        int i = (t < 49) ? t : (t - 49);
        float* row = (t < 49) ? qs[i] : ks[i];
        float ss = 0.f;
        #pragma unroll
        for (int d = 0; d < 32; d++) ss += row[d] * row[d];
        float inv = 1.f / fmaxf(sqrtf(ss), 1e-12f);
        #pragma unroll
        for (int d = 0; d < 32; d++) row[d] *= inv;
    }
    __syncthreads();
    float tauv = tau[head];
    const float* bh = g_bias + head * 2401;
    for (int idx = t; idx < 2401; idx += 256) {
        int i = idx / 49, j = idx % 49;
        float s = 0.f;
        #pragma unroll
        for (int d = 0; d < 32; d++) s += qs[i][d] * ks[j][d];
        s = s * tauv + bh[idx];
        if (lab[i] != lab[j]) s -= 100.f;
        S[i][j] = s;
    }
    __syncthreads();
    if (t < 49) {
        float m = -1e30f;
        #pragma unroll 7
        for (int j = 0; j < 49; j++) m = fmaxf(m, S[t][j]);
        float sum = 0.f;
        #pragma unroll 7
        for (int j = 0; j < 49; j++) { float e = __expf(S[t][j] - m); S[t][j] = e; sum += e; }
        float inv = 1.f / sum;
        #pragma unroll 7
        for (int j = 0; j < 49; j++) S[t][j] *= inv;
    }
    __syncthreads();
    __half* outbase = g_att + (size_t)win * 49 * D + head * 32;
    for (int idx = t; idx < 49 * 32; idx += 256) {
        int i = idx >> 5, d = idx & 31;
        float s = 0.f;
        #pragma unroll 7
        for (int j = 0; j < 49; j++) s += S[i][j] * vs[j][d];
        outbase[(size_t)i * D + d] = __float2half(s);
    }
}

// ================= launch =================
extern "C" void kernel_launch(void* const* d_in, const int* in_sizes, int n_in,
                              void* d_out, int out_size) {
    const float* x       = (const float*)d_in[0];
    const float* n1g     = (const float*)d_in[1];
    const float* n1b     = (const float*)d_in[2];
    const float* qkv_w   = (const float*)d_in[3];
    const float* qkv_b   = (const float*)d_in[4];
    const float* tau     = (const float*)d_in[5];
    const float* proj_w  = (const float*)d_in[6];
    const float* proj_b  = (const float*)d_in[7];
    const float* crpb_w1 = (const float*)d_in[8];
    const float* crpb_b1 = (const float*)d_in[9];
    const float* crpb_w2 = (const float*)d_in[10];
    const float* crpb_b2 = (const float*)d_in[11];
    const float* n2g     = (const float*)d_in[12];
    const float* n2b     = (const float*)d_in[13];
    const float* mlp_w1  = (const float*)d_in[14];
    const float* mlp_b1  = (const float*)d_in[15];
    const float* mlp_w2  = (const float*)d_in[16];
    const float* mlp_b2  = (const float*)d_in[17];
    float* out = (float*)d_out;

    __half *xw, *att, *hbuf, *wtq, *wtp, *wt1, *wt2;
    float *qkv, *x1;
    cudaGetSymbolAddress((void**)&xw,  g_xw);
    cudaGetSymbolAddress((void**)&qkv, g_qkv);
    cudaGetSymbolAddress((void**)&att, g_att);
    cudaGetSymbolAddress((void**)&x1,  g_x1);
    cudaGetSymbolAddress((void**)&hbuf, g_h);
    cudaGetSymbolAddress((void**)&wtq, g_wt_qkv);
    cudaGetSymbolAddress((void**)&wtp, g_wt_proj);
    cudaGetSymbolAddress((void**)&wt1, g_wt_m1);
    cudaGetSymbolAddress((void**)&wt2, g_wt_m2);

    static int attr_set = 0;
    if (!attr_set) {
        cudaFuncSetAttribute((const void*)gemm_tc<0, float>,  cudaFuncAttributeMaxDynamicSharedMemorySize, (int)GEMM_SMEM);
        cudaFuncSetAttribute((const void*)gemm_tc<1, __half>, cudaFuncAttributeMaxDynamicSharedMemorySize, (int)GEMM_SMEM);
        cudaFuncSetAttribute((const void*)gemm_tc<2, float>,  cudaFuncAttributeMaxDynamicSharedMemorySize, (int)GEMM_SMEM);
        cudaFuncSetAttribute((const void*)gemm_tc<3, float>,  cudaFuncAttributeMaxDynamicSharedMemorySize, (int)GEMM_SMEM);
        attr_set = 1;
    }

    const int MB = TOKENS / 256;   // 392
    dim3 tb(32, 8);

    transpose_kernel<<<dim3(D3 / 32, D / 32), tb>>>(qkv_w, wtq, D, D3);
    transpose_kernel<<<dim3(D / 32, D / 32), tb>>>(proj_w, wtp, D, D);
    transpose_kernel<<<dim3(DH / 32, D / 32), tb>>>(mlp_w1, wt1, D, DH);
    transpose_kernel<<<dim3(D / 32, DH / 32), tb>>>(mlp_w2, wt2, DH, D);
    bias_kernel<<<2401, 64>>>(crpb_w1, crpb_b1, crpb_w2, crpb_b2);

    ln_kernel<<<TOKENS, 128>>>(x, n1g, n1b, xw, 1);
    gemm_tc<0, float><<<dim3(D3 / 128, MB), 256, GEMM_SMEM>>>(xw, wtq, qkv_b, qkv, D, D3, nullptr);
    attn_kernel<<<NWIN * HEADS, 256>>>(tau);
    gemm_tc<2, float><<<dim3(D / 128, MB), 256, GEMM_SMEM>>>(att, wtp, proj_b, x1, D, D, x);
    ln_kernel<<<TOKENS, 128>>>(x1, n2g, n2b, xw, 0);
    gemm_tc<1, __half><<<dim3(DH / 128, MB), 256, GEMM_SMEM>>>(xw, wt1, mlp_b1, hbuf, D, DH, nullptr);
    gemm_tc<3, float><<<dim3(D / 128, MB), 256, GEMM_SMEM>>>(hbuf, wt2, mlp_b2, out, DH, D, x1);
}

// round 7
// speedup vs baseline: 2.8609x; 1.1090x over previous
#include <cuda_runtime.h>
#include <cuda_fp16.h>
#include <math.h>
#include <stdint.h>

#define TOKENS 100352      // 32 * 56 * 56  == 2048 windows * 49
#define D      384
#define D3     1152
#define DH     1536
#define NWIN   2048
#define HEADS  12

// -------- scratch (device globals; no allocation allowed) --------
__device__ __half g_xw [(size_t)TOKENS * D];     // LN out (half, GEMM A operand)
__device__ float  g_qkv[(size_t)TOKENS * D3];    // qkv (fp32 for attention math)
__device__ __half g_att[(size_t)TOKENS * D];     // attention out (half)
__device__ float  g_x1 [(size_t)TOKENS * D];     // proj + residual (fp32)
__device__ __half g_h  [(size_t)TOKENS * DH];    // mlp hidden (half)
__device__ float  g_bias[HEADS * 49 * 49];
// transposed + fp16 weights [N][K]
__device__ __half g_wt_qkv[D3 * D];
__device__ __half g_wt_proj[D * D];
__device__ __half g_wt_m1[DH * D];
__device__ __half g_wt_m2[D * DH];

// ================= weight transpose + fp16 convert: Wt[n][k] = W[k][n] =================
__global__ void transpose_kernel(const float* __restrict__ W, __half* __restrict__ Wt,
                                 int K, int N) {
    __shared__ float tile[32][33];
    int n0 = blockIdx.x * 32, k0 = blockIdx.y * 32;
    int tx = threadIdx.x, ty = threadIdx.y;   // 32 x 8
    #pragma unroll
    for (int i = 0; i < 32; i += 8) tile[ty + i][tx] = W[(size_t)(k0 + ty + i) * N + n0 + tx];
    __syncthreads();
    #pragma unroll
    for (int i = 0; i < 32; i += 8)
        Wt[(size_t)(n0 + ty + i) * K + k0 + tx] = __float2half(tile[tx][ty + i]);
}

// ================= CRPB bias table =================
__global__ void bias_kernel(const float* __restrict__ w1, const float* __restrict__ b1,
                            const float* __restrict__ w2, const float* __restrict__ b2) {
    int p = blockIdx.x;
    int i = p / 49, j = p % 49;
    float dr = (float)(i / 7 - j / 7);
    float dc = (float)(i % 7 - j % 7);
    float r0 = (dr == 0.f) ? 0.f : copysignf(log1pf(fabsf(dr)), dr);
    float r1 = (dc == 0.f) ? 0.f : copysignf(log1pf(fabsf(dc)), dc);
    __shared__ float hid[64];
    int t = threadIdx.x;
    if (t < 64) {
        float v = r0 * w1[t] + r1 * w1[64 + t] + b1[t];
        hid[t] = fmaxf(v, 0.f);
    }
    __syncthreads();
    if (t < HEADS) {
        float s = b2[t];
        #pragma unroll 8
        for (int k = 0; k < 64; k++) s += hid[k] * w2[k * HEADS + t];
        g_bias[t * 2401 + p] = s;
    }
}

// ================= LayerNorm -> half (optionally fused shift+window gather) =================
__global__ void ln_kernel(const float* __restrict__ x, const float* __restrict__ g,
                          const float* __restrict__ b, __half* __restrict__ out, int mapped) {
    int r = blockIdx.x;
    int src = r;
    if (mapped) {
        int win = r / 49, pos = r % 49;
        int bb = win >> 6, wrem = win & 63;
        int wh = wrem >> 3, ww = wrem & 7;
        int rr = pos / 7, cc = pos % 7;
        int sh = (wh * 7 + rr + 3) % 56;
        int sw = (ww * 7 + cc + 3) % 56;
        src = bb * 3136 + sh * 56 + sw;
    }
    const float* xr = x + (size_t)src * D;
    int t = threadIdx.x;                       // 128 threads
    float v0 = xr[t], v1 = xr[t + 128], v2 = xr[t + 256];
    float s = v0 + v1 + v2;
    __shared__ float red[4];
    __shared__ float red2[4];
    #pragma unroll
    for (int o = 16; o > 0; o >>= 1) s += __shfl_down_sync(0xffffffffu, s, o);
    if ((t & 31) == 0) red[t >> 5] = s;
    __syncthreads();
    float mu = (red[0] + red[1] + red[2] + red[3]) * (1.f / 384.f);
    float d0 = v0 - mu, d1 = v1 - mu, d2 = v2 - mu;
    float q = d0 * d0 + d1 * d1 + d2 * d2;
    #pragma unroll
    for (int o = 16; o > 0; o >>= 1) q += __shfl_down_sync(0xffffffffu, q, o);
    if ((t & 31) == 0) red2[t >> 5] = q;
    __syncthreads();
    float var = (red2[0] + red2[1] + red2[2] + red2[3]) * (1.f / 384.f);
    float inv = rsqrtf(var + 1e-5f);
    __half* orow = out + (size_t)r * D;
    orow[t]       = __float2half(d0 * inv * g[t]       + b[t]);
    orow[t + 128] = __float2half(d1 * inv * g[t + 128] + b[t + 128]);
    orow[t + 256] = __float2half(d2 * inv * g[t + 256] + b[t + 256]);
}

// ================= fp16 tensor-core GEMM, 128x128 tile, 64x32 per warp, ldmatrix =================
// C(MxN) = A(MxK) * Wt(NxK)^T + bias.  A,Wt half; fp32 accumulate.
// SMEM rows: 16 halves (8 words) + 4 pad; stride 12 words => ldmatrix phases conflict-free.
// 2 CTAs/SM (4 warps/SMSP) for HMMA pipe latency hiding.
// MODE 0: plain->f32   MODE 1: gelu->half   MODE 2: scatter+residual->f32   MODE 3: +residual->f32

#define RPAD 12                 // words per smem row
#define STAGES 3
#define A_STG (128 * RPAD)      // words
#define B_STG (128 * RPAD)
#define GEMM_SMEM ((STAGES * (A_STG + B_STG)) * 4)

__device__ __forceinline__ void mma_f16(float* c, const unsigned* a, const unsigned* b) {
    asm volatile(
        "mma.sync.aligned.m16n8k16.row.col.f32.f16.f16.f32 "
        "{%0,%1,%2,%3}, {%4,%5,%6,%7}, {%8,%9}, {%0,%1,%2,%3};"
        : "+f"(c[0]), "+f"(c[1]), "+f"(c[2]), "+f"(c[3])
        : "r"(a[0]), "r"(a[1]), "r"(a[2]), "r"(a[3]), "r"(b[0]), "r"(b[1]));
}

__device__ __forceinline__ void ldsm4(unsigned* r, uint32_t addr) {
    asm volatile("ldmatrix.sync.aligned.m8n8.x4.shared.b16 {%0,%1,%2,%3}, [%4];"
        : "=r"(r[0]), "=r"(r[1]), "=r"(r[2]), "=r"(r[3]) : "r"(addr));
}

__device__ __forceinline__ void cp16(uint32_t dst_smem, const void* src_gmem) {
    asm volatile("cp.async.ca.shared.global [%0], [%1], 16;\n" :: "r"(dst_smem), "l"(src_gmem));
}

template <int MODE, typename OutT>
__global__ __launch_bounds__(256, 2) void gemm_tc(
    const __half* __restrict__ A, const __half* __restrict__ Wt,
    const float* __restrict__ bias, OutT* __restrict__ C,
    int K, int N, const float* __restrict__ add) {
    extern __shared__ unsigned sm[];
    uint32_t smb = (uint32_t)__cvta_generic_to_shared(sm);

    int tid = threadIdx.x;
    int lane = tid & 31, warp = tid >> 5;
    int bm = blockIdx.y * 128, bn = blockIdx.x * 128;
    int wm = (warp & 1) * 64, wn = (warp >> 1) * 32;

    float acc[4][4][4];
    #pragma unroll
    for (int i = 0; i < 4; i++)
        #pragma unroll
        for (int j = 0; j < 4; j++)
            #pragma unroll
            for (int l = 0; l < 4; l++) acc[i][j][l] = 0.f;

    // ldmatrix source offsets (bytes, within a stage)
    uint32_t a_off[4], b_off[2];
    #pragma unroll
    for (int mi = 0; mi < 4; mi++)
        a_off[mi] = ((wm + mi * 16 + (lane & 15)) * RPAD + (lane >> 4) * 4) * 4;
    #pragma unroll
    for (int bi = 0; bi < 2; bi++)
        b_off[bi] = ((wn + bi * 16 + (lane & 7) + ((lane >> 4) * 8)) * RPAD
                     + ((lane >> 3) & 1) * 4) * 4;

    // staging: A 128 rows x 32B = 256 16B-chunks; B same. 256 threads -> 1 chunk each.
    int srow = tid >> 1, schunk = tid & 1;
    auto stage_copy = [&](int s, int k0) {
        uint32_t as = smb + (s * A_STG) * 4;
        uint32_t bs = smb + (STAGES * A_STG + s * B_STG) * 4;
        cp16(as + (srow * RPAD + schunk * 4) * 4,
             A + (size_t)(bm + srow) * K + k0 + schunk * 8);
        cp16(bs + (srow * RPAD + schunk * 4) * 4,
             Wt + (size_t)(bn + srow) * K + k0 + schunk * 8);
    };

    stage_copy(0, 0);
    asm volatile("cp.async.commit_group;\n" ::);
    stage_copy(1, 16);
    asm volatile("cp.async.commit_group;\n" ::);

    int nit = K / 16;
    for (int it = 0; it < nit; it++) {
        asm volatile("cp.async.wait_group 1;\n" ::);
        __syncthreads();
        int nk = it + 2;
        if (nk < nit) stage_copy(nk % STAGES, nk * 16);
        asm volatile("cp.async.commit_group;\n" ::);

        int s = it % STAGES;
        uint32_t as = smb + (s * A_STG) * 4;
        uint32_t bs = smb + (STAGES * A_STG + s * B_STG) * 4;

        unsigned af[4][4];
        #pragma unroll
        for (int mi = 0; mi < 4; mi++) ldsm4(af[mi], as + a_off[mi]);
        unsigned bf[4][2];
        #pragma unroll
        for (int bi = 0; bi < 2; bi++) {
            unsigned q[4];
            ldsm4(q, bs + b_off[bi]);
            bf[bi * 2 + 0][0] = q[0]; bf[bi * 2 + 0][1] = q[1];
            bf[bi * 2 + 1][0] = q[2]; bf[bi * 2 + 1][1] = q[3];
        }
        #pragma unroll
        for (int mi = 0; mi < 4; mi++)
            #pragma unroll
            for (int ni = 0; ni < 4; ni++)
                mma_f16(acc[mi][ni], af[mi], bf[ni]);
        __syncthreads();
    }

    // ---------- epilogue ----------
    int km = lane & 3;
    int mrow = lane >> 2;
    int cbase = bn + wn + 2 * km;
    #pragma unroll
    for (int mi = 0; mi < 4; mi++) {
        #pragma unroll
        for (int half = 0; half < 2; half++) {
            int row = bm + wm + mi * 16 + mrow + half * 8;
            int dst = row;
            if (MODE == 2) {
                int win = row / 49, pos = row % 49;
                int bb = win >> 6, wrem = win & 63;
                int wh = wrem >> 3, ww = wrem & 7;
                int rr = pos / 7, cc = pos % 7;
                dst = bb * 3136 + ((wh * 7 + rr + 3) % 56) * 56 + ((ww * 7 + cc + 3) % 56);
            }
            OutT* cp = C + (size_t)dst * N;
            const float* ap = (MODE == 2 || MODE == 3) ? add + (size_t)dst * N : nullptr;
            #pragma unroll
            for (int ni = 0; ni < 4; ni++) {
                int col = cbase + ni * 8;
                float v0 = acc[mi][ni][half * 2 + 0] + bias[col];
                float v1 = acc[mi][ni][half * 2 + 1] + bias[col + 1];
                if (MODE == 1) {
                    v0 = 0.5f * v0 * (1.f + erff(v0 * 0.70710678118654752f));
                    v1 = 0.5f * v1 * (1.f + erff(v1 * 0.70710678118654752f));
                }
                if (MODE == 2 || MODE == 3) {
                    v0 += ap[col];
                    v1 += ap[col + 1];
                }
                if (sizeof(OutT) == 2) {
                    __half2 o = __floats2half2_rn(v0, v1);
                    *(__half2*)((__half*)cp + col) = o;
                } else {
                    float2 o = {v0, v1};
                    *(float2*)((float*)cp + col) = o;
                }
            }
        }
    }
}

// ================= window attention: one block per (window, head) =================
__global__ void attn_kernel(const float* __restrict__ tau) {
    int blk = blockIdx.x;
    int win = blk / HEADS;
    int head = blk % HEADS;
    __shared__ float qs[49][32], ks[49][32], vs[49][32];
    __shared__ float S[49][52];
    __shared__ int lab[49];
    int t = threadIdx.x;                // 256
    int wrem = win & 63;
    int wh = wrem >> 3, ww = wrem & 7;
    if (t < 49) {
        int rr = t / 7, cc = t % 7;
        int h = wh * 7 + rr, w = ww * 7 + cc;
        int hs = (h < 49) ? 0 : ((h < 53) ? 1 : 2);
        int wsg = (w < 49) ? 0 : ((w < 53) ? 1 : 2);
        lab[t] = hs * 3 + wsg;
    }
    const float* base = g_qkv + (size_t)win * 49 * D3 + head * 32;
    for (int idx = t; idx < 49 * 32; idx += 256) {
        int i = idx >> 5, d = idx & 31;
        const float* p = base + (size_t)i * D3 + d;
        qs[i][d] = p[0];
        ks[i][d] = p[384];
        vs[i][d] = p[768];
    }
    __syncthreads();
    if (t < 98) {
        int i = (t < 49) ? t : (t - 49);
        float* row = (t < 49) ? qs[i] : ks[i];
        float ss = 0.f;
        #pragma unroll
        for (int d = 0; d < 32; d++) ss += row[d] * row[d];
        float inv = 1.f / fmaxf(sqrtf(ss), 1e-12f);
        #pragma unroll
        for (int d = 0; d < 32; d++) row[d] *= inv;
    }
    __syncthreads();
    float tauv = tau[head];
    const float* bh = g_bias + head * 2401;
    for (int idx = t; idx < 2401; idx += 256) {
        int i = idx / 49, j = idx % 49;
        float s = 0.f;
        #pragma unroll
        for (int d = 0; d < 32; d++) s += qs[i][d] * ks[j][d];
        s = s * tauv + bh[idx];
        if (lab[i] != lab[j]) s -= 100.f;
        S[i][j] = s;
    }
    __syncthreads();
    if (t < 49) {
        float m = -1e30f;
        #pragma unroll 7
        for (int j = 0; j < 49; j++) m = fmaxf(m, S[t][j]);
        float sum = 0.f;
        #pragma unroll 7
        for (int j = 0; j < 49; j++) { float e = __expf(S[t][j] - m); S[t][j] = e; sum += e; }
        float inv = 1.f / sum;
        #pragma unroll 7
        for (int j = 0; j < 49; j++) S[t][j] *= inv;
    }
    __syncthreads();
    __half* outbase = g_att + (size_t)win * 49 * D + head * 32;
    for (int idx = t; idx < 49 * 32; idx += 256) {
        int i = idx >> 5, d = idx & 31;
        float s = 0.f;
        #pragma unroll 7
        for (int j = 0; j < 49; j++) s += S[i][j] * vs[j][d];
        outbase[(size_t)i * D + d] = __float2half(s);
    }
}

// ================= launch =================
extern "C" void kernel_launch(void* const* d_in, const int* in_sizes, int n_in,
                              void* d_out, int out_size) {
    const float* x       = (const float*)d_in[0];
    const float* n1g     = (const float*)d_in[1];
    const float* n1b     = (const float*)d_in[2];
    const float* qkv_w   = (const float*)d_in[3];
    const float* qkv_b   = (const float*)d_in[4];
    const float* tau     = (const float*)d_in[5];
    const float* proj_w  = (const float*)d_in[6];
    const float* proj_b  = (const float*)d_in[7];
    const float* crpb_w1 = (const float*)d_in[8];
    const float* crpb_b1 = (const float*)d_in[9];
    const float* crpb_w2 = (const float*)d_in[10];
    const float* crpb_b2 = (const float*)d_in[11];
    const float* n2g     = (const float*)d_in[12];
    const float* n2b     = (const float*)d_in[13];
    const float* mlp_w1  = (const float*)d_in[14];
    const float* mlp_b1  = (const float*)d_in[15];
    const float* mlp_w2  = (const float*)d_in[16];
    const float* mlp_b2  = (const float*)d_in[17];
    float* out = (float*)d_out;

    __half *xw, *att, *hbuf, *wtq, *wtp, *wt1, *wt2;
    float *qkv, *x1;
    cudaGetSymbolAddress((void**)&xw,  g_xw);
    cudaGetSymbolAddress((void**)&qkv, g_qkv);
    cudaGetSymbolAddress((void**)&att, g_att);
    cudaGetSymbolAddress((void**)&x1,  g_x1);
    cudaGetSymbolAddress((void**)&hbuf, g_h);
    cudaGetSymbolAddress((void**)&wtq, g_wt_qkv);
    cudaGetSymbolAddress((void**)&wtp, g_wt_proj);
    cudaGetSymbolAddress((void**)&wt1, g_wt_m1);
    cudaGetSymbolAddress((void**)&wt2, g_wt_m2);

    static int attr_set = 0;
    if (!attr_set) {
        cudaFuncSetAttribute((const void*)gemm_tc<0, float>,  cudaFuncAttributeMaxDynamicSharedMemorySize, (int)GEMM_SMEM);
        cudaFuncSetAttribute((const void*)gemm_tc<1, __half>, cudaFuncAttributeMaxDynamicSharedMemorySize, (int)GEMM_SMEM);
        cudaFuncSetAttribute((const void*)gemm_tc<2, float>,  cudaFuncAttributeMaxDynamicSharedMemorySize, (int)GEMM_SMEM);
        cudaFuncSetAttribute((const void*)gemm_tc<3, float>,  cudaFuncAttributeMaxDynamicSharedMemorySize, (int)GEMM_SMEM);
        attr_set = 1;
    }

    const int MB = TOKENS / 128;   // 784
    dim3 tb(32, 8);

    transpose_kernel<<<dim3(D3 / 32, D / 32), tb>>>(qkv_w, wtq, D, D3);
    transpose_kernel<<<dim3(D / 32, D / 32), tb>>>(proj_w, wtp, D, D);
    transpose_kernel<<<dim3(DH / 32, D / 32), tb>>>(mlp_w1, wt1, D, DH);
    transpose_kernel<<<dim3(D / 32, DH / 32), tb>>>(mlp_w2, wt2, DH, D);
    bias_kernel<<<2401, 64>>>(crpb_w1, crpb_b1, crpb_w2, crpb_b2);

    ln_kernel<<<TOKENS, 128>>>(x, n1g, n1b, xw, 1);
    gemm_tc<0, float><<<dim3(D3 / 128, MB), 256, GEMM_SMEM>>>(xw, wtq, qkv_b, qkv, D, D3, nullptr);
    attn_kernel<<<NWIN * HEADS, 256>>>(tau);
    gemm_tc<2, float><<<dim3(D / 128, MB), 256, GEMM_SMEM>>>(att, wtp, proj_b, x1, D, D, x);
    ln_kernel<<<TOKENS, 128>>>(x1, n2g, n2b, xw, 0);
    gemm_tc<1, __half><<<dim3(DH / 128, MB), 256, GEMM_SMEM>>>(xw, wt1, mlp_b1, hbuf, D, DH, nullptr);
    gemm_tc<3, float><<<dim3(D / 128, MB), 256, GEMM_SMEM>>>(hbuf, wt2, mlp_b2, out, DH, D, x1);
}